// round 7
// baseline (speedup 1.0000x reference)
#include <cuda_runtime.h>
#include <math.h>

// x: [B=4, C=64, H=64, W=64, D=64] fp32
// out = x + irfftn(delta), delta = (gate-1)*rfftn(x) on corner [16,16,9]
#define NPLANES 16384   // B*C*H
#define GATE_DIM 2304   // 16*16*9
#define NCOL    144     // 16 ky * 9 kz

__device__ float2 g_Y[NPLANES * NCOL];     // 18.9 MB intermediate spectrum
__device__ float  g_planesum[NPLANES];
__device__ float  g_hid[64];               // hidden layer [b*16+j]
__device__ float  g_gate[4 * GATE_DIM];    // (sigmoid-1)/64^3

#define INV_N3 (1.0f / 262144.0f)

// runtime twiddle table in smem: tw[t] = (cos(2*pi*t/64), sin(2*pi*t/64))
__device__ __forceinline__ void fill_tw(float2* tw, int tid) {
    if (tid < 64) {
        float s, c;
        sincospif((float)tid * (1.0f / 32.0f), &s, &c);
        tw[tid] = make_float2(c, s);
    }
}

// ---------------------------------------------------------------------------
// Kernel 1: per-plane (b,c,h): plane sum, folded z-DFT, folded y-DFT
// (y-DFT split into 288 half-range tasks for full thread utilization)
// ---------------------------------------------------------------------------
__global__ void __launch_bounds__(256) k_fwd(const float* __restrict__ x) {
    __shared__ float  xs[64 * 65];        // [w][d], stride 65
    __shared__ float2 Zs[64 * 9];         // [w][kz]
    __shared__ float2 Ypart[288];         // y-DFT halves
    __shared__ float2 tw[64];
    __shared__ float  red[8];

    const int plane = blockIdx.x;
    const int tid   = threadIdx.x;
    fill_tw(tw, tid);

    // Vectorized plane load + pooling sum
    const float4* xp4 = (const float4*)(x + (size_t)plane * 4096);
    float psum = 0.0f;
    #pragma unroll
    for (int k = 0; k < 4; k++) {
        const int i4 = k * 256 + tid;
        float4 v = xp4[i4];
        const int base = i4 * 4;
        float* dst = &xs[(base >> 6) * 65 + (base & 63)];
        dst[0] = v.x; dst[1] = v.y; dst[2] = v.z; dst[3] = v.w;
        psum += (v.x + v.y) + (v.z + v.w);
    }
    #pragma unroll
    for (int o = 16; o > 0; o >>= 1) psum += __shfl_down_sync(0xffffffffu, psum, o);
    if ((tid & 31) == 0) red[tid >> 5] = psum;
    __syncthreads();
    if (tid == 0) {
        float s = 0.0f;
        #pragma unroll
        for (int i = 0; i < 8; i++) s += red[i];
        g_planesum[plane] = s;
    }

    // Folded z-DFT: thread (g = tid>>6, w = tid&63); kz in {g, g+4, 8 if g==0}
    {
        const int w = tid & 63;
        const int g = tid >> 6;
        const int kz0 = g, kz1 = g + 4;
        const float sg0 = (kz0 & 1) ? -1.0f : 1.0f;
        const float sg1 = (kz1 & 1) ? -1.0f : 1.0f;
        const float* row = &xs[w * 65];
        const float x0 = row[0], x32 = row[32];
        float re0 = x0 + sg0 * x32, im0 = 0.f;
        float re1 = x0 + sg1 * x32, im1 = 0.f;
        float re2 = x0 + x32,       im2 = 0.f;        // kz=8
        #pragma unroll 31
        for (int dp = 1; dp <= 31; dp++) {
            float a = row[dp], b = row[64 - dp];
            float e = a + b, o = a - b;
            float2 t0 = tw[(kz0 * dp) & 63];
            re0 = fmaf(e, t0.x, re0); im0 = fmaf(-o, t0.y, im0);
            float2 t1 = tw[(kz1 * dp) & 63];
            re1 = fmaf(e, t1.x, re1); im1 = fmaf(-o, t1.y, im1);
            if (g == 0) {
                float2 t2 = tw[(8 * dp) & 63];
                re2 = fmaf(e, t2.x, re2); im2 = fmaf(-o, t2.y, im2);
            }
        }
        Zs[w * 9 + kz0] = make_float2(re0, im0);
        Zs[w * 9 + kz1] = make_float2(re1, im1);
        if (g == 0) Zs[w * 9 + 8] = make_float2(re2, im2);
    }
    __syncthreads();

    // Folded y-DFT, 288 half-range tasks:
    //   j <  144: wp = 1..16 plus the w=0 / w=32 edge terms
    //   j >= 144: wp = 17..31
    for (int j = tid; j < 288; j += 256) {
        float re = 0.f, im = 0.f;
        if (j < 144) {
            const int ky = j / 9, kz = j - ky * 9;
            float2 z0 = Zs[kz], z32 = Zs[32 * 9 + kz];
            const float sg = (ky & 1) ? -1.0f : 1.0f;
            re = fmaf(sg, z32.x, z0.x);
            im = fmaf(sg, z32.y, z0.y);
            #pragma unroll
            for (int wp = 1; wp <= 16; wp++) {
                float2 za = Zs[wp * 9 + kz];
                float2 zb = Zs[(64 - wp) * 9 + kz];
                float sx = za.x + zb.x, dxx = za.x - zb.x;
                float sy = za.y + zb.y, dy  = za.y - zb.y;
                float2 t = tw[(ky * wp) & 63];
                re = fmaf(sx, t.x, re); re = fmaf(dy, t.y, re);
                im = fmaf(sy, t.x, im); im = fmaf(-dxx, t.y, im);
            }
        } else {
            const int m = j - 144;
            const int ky = m / 9, kz = m - ky * 9;
            #pragma unroll
            for (int wp = 17; wp <= 31; wp++) {
                float2 za = Zs[wp * 9 + kz];
                float2 zb = Zs[(64 - wp) * 9 + kz];
                float sx = za.x + zb.x, dxx = za.x - zb.x;
                float sy = za.y + zb.y, dy  = za.y - zb.y;
                float2 t = tw[(ky * wp) & 63];
                re = fmaf(sx, t.x, re); re = fmaf(dy, t.y, re);
                im = fmaf(sy, t.x, im); im = fmaf(-dxx, t.y, im);
            }
        }
        Ypart[j] = make_float2(re, im);
    }
    __syncthreads();
    if (tid < NCOL) {
        float2 a = Ypart[tid], b = Ypart[tid + 144];
        g_Y[(size_t)plane * NCOL + tid] = make_float2(a.x + b.x, a.y + b.y);
    }
}

// ---------------------------------------------------------------------------
// Kernel 2a: pooled -> hidden (1 block)
// ---------------------------------------------------------------------------
__global__ void __launch_bounds__(256) k_gates1(const float* __restrict__ w1,
                                                const float* __restrict__ b1) {
    __shared__ float pooled_s[256];
    const int tid = threadIdx.x;
    {
        float s = 0.0f;
        const float* ps = &g_planesum[tid * 64];
        #pragma unroll 8
        for (int h = 0; h < 64; h++) s += ps[h];
        pooled_s[tid] = s * INV_N3;
    }
    __syncthreads();
    if (tid < 64) {
        const int b = tid >> 4, j = tid & 15;
        float acc = b1[j];
        #pragma unroll 8
        for (int c = 0; c < 64; c++) acc = fmaf(pooled_s[b * 64 + c], w1[c * 16 + j], acc);
        g_hid[tid] = fmaxf(acc, 0.0f);
    }
}

// ---------------------------------------------------------------------------
// Kernel 2b: hidden -> gates (grid 36)
// ---------------------------------------------------------------------------
__global__ void __launch_bounds__(256) k_gates2(const float* __restrict__ w2,
                                                const float* __restrict__ b2) {
    const int j2 = blockIdx.x * 256 + threadIdx.x;   // 0..9215
    const int b = j2 / GATE_DIM, m = j2 - b * GATE_DIM;
    float acc = b2[m];
    #pragma unroll
    for (int j = 0; j < 16; j++) acc = fmaf(g_hid[b * 16 + j], w2[j * GATE_DIM + m], acc);
    float sig = 1.0f / (1.0f + expf(-acc));
    g_gate[j2] = (sig - 1.0f) * INV_N3;
}

// ---------------------------------------------------------------------------
// Kernel 3: per (bc, 36-mode chunk): folded x-DFT -> gate -> folded x-inverse
// ---------------------------------------------------------------------------
#define MCH 36
__global__ void __launch_bounds__(256) k_xstage() {
    __shared__ float2 Ys[64 * MCH];
    __shared__ float2 As[MCH * 17];
    __shared__ float2 tw[64];

    const int bx  = blockIdx.x;
    const int bc  = bx >> 2;
    const int b   = bc >> 6;
    const int m0  = (bx & 3) * MCH;
    const int tid = threadIdx.x;
    fill_tw(tw, tid);

    float2* Yg = &g_Y[(size_t)bc * 64 * NCOL];
    for (int j = tid; j < 64 * MCH; j += 256) {
        const int h = j / MCH, mL = j % MCH;
        Ys[j] = Yg[h * NCOL + m0 + mL];
    }
    __syncthreads();

    for (int j = tid; j < MCH * 16; j += 256) {
        const int kx = j / MCH;
        const int mL = j % MCH;
        const float sg = (kx & 1) ? -1.0f : 1.0f;
        float2 z0 = Ys[mL], z32 = Ys[32 * MCH + mL];
        float re = fmaf(sg, z32.x, z0.x);
        float im = fmaf(sg, z32.y, z0.y);
        #pragma unroll 31
        for (int hp = 1; hp <= 31; hp++) {
            float2 za = Ys[hp * MCH + mL];
            float2 zb = Ys[(64 - hp) * MCH + mL];
            float sx = za.x + zb.x, dxx = za.x - zb.x;
            float sy = za.y + zb.y, dy  = za.y - zb.y;
            float2 t = tw[(kx * hp) & 63];
            re = fmaf(sx, t.x, re); re = fmaf(dy, t.y, re);
            im = fmaf(sy, t.x, im); im = fmaf(-dxx, t.y, im);
        }
        float gate = g_gate[b * GATE_DIM + kx * NCOL + m0 + mL];
        As[mL * 17 + kx] = make_float2(re * gate, im * gate);
    }
    __syncthreads();

    for (int j = tid; j < 32 * MCH; j += 256) {
        const int hp = j / MCH;
        const int mL = j % MCH;
        float P = 0.f, Q = 0.f, R = 0.f, S = 0.f;
        #pragma unroll
        for (int kx = 0; kx < 16; kx++) {
            float2 A = As[mL * 17 + kx];
            float2 t = tw[(kx * hp) & 63];
            P = fmaf(A.x, t.x, P); Q = fmaf(A.y, t.y, Q);
            R = fmaf(A.y, t.x, R); S = fmaf(A.x, t.y, S);
        }
        if (hp == 0) {
            float P32 = 0.f, R32 = 0.f;
            #pragma unroll
            for (int kx = 0; kx < 16; kx++) {
                float2 A = As[mL * 17 + kx];
                float sg = (kx & 1) ? -1.0f : 1.0f;
                P32 = fmaf(A.x, sg, P32); R32 = fmaf(A.y, sg, R32);
            }
            Yg[m0 + mL]             = make_float2(P, R);
            Yg[32 * NCOL + m0 + mL] = make_float2(P32, R32);
        } else {
            Yg[hp * NCOL + m0 + mL]        = make_float2(P - Q, S + R);
            Yg[(64 - hp) * NCOL + m0 + mL] = make_float2(P + Q, R - S);
        }
    }
}

// ---------------------------------------------------------------------------
// Kernel 4: per-plane: folded y-inverse (float4 Yrow), folded z-synthesis
// ---------------------------------------------------------------------------
__global__ void __launch_bounds__(256) k_inv(const float* __restrict__ x,
                                             float* __restrict__ out) {
    __shared__ __align__(16) float2 Yrow2[9 * 16];   // [kz][ky]
    __shared__ float2 B2s[64 * 9];                   // [w][kz]
    __shared__ float2 tw[64];

    const int plane = blockIdx.x;
    const int tid   = threadIdx.x;
    fill_tw(tw, tid);
    if (tid < NCOL) {
        const int ky = tid / 9, kz = tid - ky * 9;
        Yrow2[kz * 16 + ky] = g_Y[(size_t)plane * NCOL + tid];
    }
    __syncthreads();

    // Folded y-inverse: tasks 0..278 generic pairs, 279..287 w=0, 288..296 w=32
    for (int j = tid; j < 297; j += 256) {
        if (j < 279) {
            const int wp = j / 9 + 1;
            const int kz = j - (wp - 1) * 9;
            const float4* yp = (const float4*)&Yrow2[kz * 16];
            float rc = 0.f, rs = 0.f, ic = 0.f, is_ = 0.f;
            #pragma unroll
            for (int kh = 0; kh < 8; kh++) {
                float4 v = yp[kh];                 // (re,im) for ky=2kh, 2kh+1
                float2 t0 = tw[((2 * kh) * wp) & 63];
                float2 t1 = tw[((2 * kh + 1) * wp) & 63];
                rc = fmaf(v.x, t0.x, rc); rs  = fmaf(v.y, t0.y, rs);
                ic = fmaf(v.y, t0.x, ic); is_ = fmaf(v.x, t0.y, is_);
                rc = fmaf(v.z, t1.x, rc); rs  = fmaf(v.w, t1.y, rs);
                ic = fmaf(v.w, t1.x, ic); is_ = fmaf(v.z, t1.y, is_);
            }
            B2s[wp * 9 + kz]        = make_float2(rc - rs, is_ + ic);
            B2s[(64 - wp) * 9 + kz] = make_float2(rc + rs, ic - is_);
        } else if (j < 288) {
            const int kz = j - 279;                // w = 0: twiddle = 1
            const float4* yp = (const float4*)&Yrow2[kz * 16];
            float re = 0.f, im = 0.f;
            #pragma unroll
            for (int kh = 0; kh < 8; kh++) { float4 v = yp[kh]; re += v.x + v.z; im += v.y + v.w; }
            B2s[kz] = make_float2(re, im);
        } else {
            const int kz = j - 288;                // w = 32: twiddle = (-1)^ky
            const float4* yp = (const float4*)&Yrow2[kz * 16];
            float re = 0.f, im = 0.f;
            #pragma unroll
            for (int kh = 0; kh < 8; kh++) { float4 v = yp[kh]; re += v.x - v.z; im += v.y - v.w; }
            B2s[32 * 9 + kz] = make_float2(re, im);
        }
    }
    __syncthreads();

    // Folded z-synthesis: lane dp handles d=dp and d=64-dp (dp=0 -> d=0 and 32)
    const int dp = tid & 31;
    const int wg = tid >> 5;              // warp id: w uniform per warp
    float cs[8], ss[8];
    #pragma unroll
    for (int kz = 1; kz <= 8; kz++) {
        float2 t = tw[(kz * dp) & 63];
        cs[kz - 1] = t.x; ss[kz - 1] = t.y;
    }
    const size_t base = (size_t)plane * 4096;
    const int d2 = (dp == 0) ? 32 : (64 - dp);
    #pragma unroll
    for (int k = 0; k < 8; k++) {
        const int w = wg * 8 + k;
        float2 Br[9];
        #pragma unroll
        for (int kz = 0; kz < 9; kz++) Br[kz] = B2s[w * 9 + kz];  // broadcast
        float Ac = 0.f, Asum = 0.f;
        #pragma unroll
        for (int kz = 1; kz <= 8; kz++) {
            Ac   = fmaf(Br[kz].x, cs[kz - 1], Ac);
            Asum = fmaf(Br[kz].y, ss[kz - 1], Asum);
        }
        const float b0 = Br[0].x;
        float v1 = fmaf(2.0f, Ac - Asum, b0);
        float v2 = fmaf(2.0f, Ac + Asum, b0);
        if (dp == 0) {
            float A32 = 0.f;
            #pragma unroll
            for (int kz = 1; kz <= 8; kz++) {
                float sg = (kz & 1) ? -1.0f : 1.0f;
                A32 = fmaf(Br[kz].x, sg, A32);
            }
            v2 = fmaf(2.0f, A32, b0);
        }
        const size_t i1 = base + (size_t)w * 64 + dp;
        const size_t i2 = base + (size_t)w * 64 + d2;
        out[i1] = x[i1] + v1;
        out[i2] = x[i2] + v2;
    }
}

// ---------------------------------------------------------------------------
extern "C" void kernel_launch(void* const* d_in, const int* in_sizes, int n_in,
                              void* d_out, int out_size) {
    const float* x  = (const float*)d_in[0];
    const float* w1 = (const float*)d_in[1];
    const float* b1 = (const float*)d_in[2];
    const float* w2 = (const float*)d_in[3];
    const float* b2 = (const float*)d_in[4];
    float* out = (float*)d_out;

    k_fwd<<<NPLANES, 256>>>(x);
    k_gates1<<<1, 256>>>(w1, b1);
    k_gates2<<<36, 256>>>(w2, b2);
    k_xstage<<<1024, 256>>>();
    k_inv<<<NPLANES, 256>>>(x, out);
}

// round 8
// speedup vs baseline: 1.4230x; 1.4230x over previous
#include <cuda_runtime.h>
#include <math.h>

// x: [B=4, C=64, H=64, W=64, D=64] fp32
// out = x + irfftn(delta), delta = (gate-1)*rfftn(x) on corner [16,16,9]
#define NPLANES 16384   // B*C*H
#define GATE_DIM 2304   // 16*16*9
#define NCOL    144     // 16 ky * 9 kz

__device__ float2 g_Y[NPLANES * NCOL];     // 18.9 MB intermediate spectrum
__device__ float  g_planesum[NPLANES];
__device__ float  g_gate[4 * GATE_DIM];    // (sigmoid-1)/64^3

#define INV_N3 (1.0f / 262144.0f)

// Compile-time twiddles: TWC[t] = cos(2*pi*t/64); sin(t) = cos(t-16) = TWC[(t+48)&63]
__device__ constexpr float TWC[64] = {
     1.00000000f,  0.99518473f,  0.98078528f,  0.95694034f,
     0.92387953f,  0.88192126f,  0.83146961f,  0.77301045f,
     0.70710678f,  0.63439328f,  0.55557023f,  0.47139674f,
     0.38268343f,  0.29028468f,  0.19509032f,  0.09801714f,
     0.00000000f, -0.09801714f, -0.19509032f, -0.29028468f,
    -0.38268343f, -0.47139674f, -0.55557023f, -0.63439328f,
    -0.70710678f, -0.77301045f, -0.83146961f, -0.88192126f,
    -0.92387953f, -0.95694034f, -0.98078528f, -0.99518473f,
    -1.00000000f, -0.99518473f, -0.98078528f, -0.95694034f,
    -0.92387953f, -0.88192126f, -0.83146961f, -0.77301045f,
    -0.70710678f, -0.63439328f, -0.55557023f, -0.47139674f,
    -0.38268343f, -0.29028468f, -0.19509032f, -0.09801714f,
     0.00000000f,  0.09801714f,  0.19509032f,  0.29028468f,
     0.38268343f,  0.47139674f,  0.55557023f,  0.63439328f,
     0.70710678f,  0.77301045f,  0.83146961f,  0.88192126f,
     0.92387953f,  0.95694034f,  0.98078528f,  0.99518473f
};
__device__ __forceinline__ constexpr float twc(int t) { return TWC[t & 63]; }
__device__ __forceinline__ constexpr float tws(int t) { return TWC[(t + 48) & 63]; }

// runtime twiddle table in smem: tw[t] = (cos(2*pi*t/64), sin(2*pi*t/64))
__device__ __forceinline__ void fill_tw(float2* tw, int tid) {
    if (tid < 64) {
        float s, c;
        sincospif((float)tid * (1.0f / 32.0f), &s, &c);
        tw[tid] = make_float2(c, s);
    }
}

// Folded z-DFT chunk: dp in [DP0, DP0+NDP), all 9 kz, compile-time twiddles.
template<int DP0, int NDP>
__device__ __forceinline__ void zchunk(const float* __restrict__ row,
                                       float* re, float* im) {
    #pragma unroll
    for (int i = 0; i < NDP; i++) {
        const int dp = DP0 + i;
        const float a = row[dp], b = row[64 - dp];
        const float e = a + b, o = a - b;
        re[0] += e;
        #pragma unroll
        for (int kz = 1; kz < 9; kz++) {
            re[kz] = fmaf(e, twc(kz * dp), re[kz]);
            im[kz] = fmaf(o, -tws(kz * dp), im[kz]);
        }
    }
}

// ---------------------------------------------------------------------------
// Kernel 1: per-plane (b,c,h): plane sum, z-DFT (immediate twiddles, chunked
// over dp, smem partial combine), y-DFT (folded, 144 threads, like R2-348).
// ---------------------------------------------------------------------------
__global__ void __launch_bounds__(256) k_fwd(const float* __restrict__ x) {
    __shared__ __align__(16) float xs[64 * 65];   // [w][d] stride 65; reused as Zs
    __shared__ float2 Zpart[4 * 64 * 9];          // [q][w][kz]
    __shared__ float2 tw[64];
    __shared__ float  red[8];
    float2* Zs = (float2*)xs;                     // overlay (xs dead after z-phase)

    const int plane = blockIdx.x;
    const int tid   = threadIdx.x;
    fill_tw(tw, tid);

    // Vectorized plane load + pooling sum
    const float4* xp4 = (const float4*)(x + (size_t)plane * 4096);
    float psum = 0.0f;
    #pragma unroll
    for (int k = 0; k < 4; k++) {
        const int i4 = k * 256 + tid;
        float4 v = xp4[i4];
        const int base = i4 * 4;
        float* dst = &xs[(base >> 6) * 65 + (base & 63)];
        dst[0] = v.x; dst[1] = v.y; dst[2] = v.z; dst[3] = v.w;
        psum += (v.x + v.y) + (v.z + v.w);
    }
    #pragma unroll
    for (int o = 16; o > 0; o >>= 1) psum += __shfl_down_sync(0xffffffffu, psum, o);
    if ((tid & 31) == 0) red[tid >> 5] = psum;
    __syncthreads();
    if (tid == 0) {
        float s = 0.0f;
        #pragma unroll
        for (int i = 0; i < 8; i++) s += red[i];
        g_planesum[plane] = s;
    }

    // z-DFT: thread (w = tid&63, q = tid>>6): 8-wide dp chunk, all 9 kz,
    // twiddles are FFMA immediates (rt=1), zero twiddle LDS.
    {
        const int w = tid & 63;
        const int q = tid >> 6;
        float re[9], im[9];
        #pragma unroll
        for (int kz = 0; kz < 9; kz++) { re[kz] = 0.f; im[kz] = 0.f; }
        const float* row = &xs[w * 65];
        if (q == 0)      zchunk<1, 8>(row, re, im);
        else if (q == 1) zchunk<9, 8>(row, re, im);
        else if (q == 2) zchunk<17, 8>(row, re, im);
        else {
            zchunk<25, 7>(row, re, im);
            const float x0 = row[0], x32 = row[32];
            #pragma unroll
            for (int kz = 0; kz < 9; kz++)
                re[kz] += x0 + ((kz & 1) ? -x32 : x32);
        }
        float2* zp = &Zpart[(q * 64 + w) * 9];
        #pragma unroll
        for (int kz = 0; kz < 9; kz++) zp[kz] = make_float2(re[kz], im[kz]);
    }
    __syncthreads();

    // Combine 4 partials -> Zs[w][kz] (overlaid on xs)
    for (int j = tid; j < 576; j += 256) {
        const int ww = j / 9, kz = j - ww * 9;
        float2 a = Zpart[ww * 9 + kz];
        float2 b = Zpart[(64 + ww) * 9 + kz];
        float2 c = Zpart[(128 + ww) * 9 + kz];
        float2 d = Zpart[(192 + ww) * 9 + kz];
        Zs[ww * 9 + kz] = make_float2((a.x + b.x) + (c.x + d.x),
                                      (a.y + b.y) + (c.y + d.y));
    }
    __syncthreads();

    // Folded y-DFT: 144 outputs (ky,kz) — identical to the 348us baseline
    if (tid < NCOL) {
        const int ky = tid / 9;
        const int kz = tid % 9;
        const float sg = (ky & 1) ? -1.0f : 1.0f;
        float2 z0 = Zs[kz], z32 = Zs[32 * 9 + kz];
        float re = fmaf(sg, z32.x, z0.x);
        float im = fmaf(sg, z32.y, z0.y);
        #pragma unroll 31
        for (int wp = 1; wp <= 31; wp++) {
            float2 za = Zs[wp * 9 + kz];
            float2 zb = Zs[(64 - wp) * 9 + kz];
            float sx = za.x + zb.x, dxx = za.x - zb.x;
            float sy = za.y + zb.y, dy  = za.y - zb.y;
            float2 t = tw[(ky * wp) & 63];
            re = fmaf(sx, t.x, re); re = fmaf(dy, t.y, re);
            im = fmaf(sy, t.x, im); im = fmaf(-dxx, t.y, im);
        }
        g_Y[(size_t)plane * NCOL + tid] = make_float2(re, im);
    }
}

// ---------------------------------------------------------------------------
// Kernel 2: gate MLP (single block) — identical to the 348us baseline
// ---------------------------------------------------------------------------
__global__ void __launch_bounds__(256) k_gates(const float* __restrict__ w1,
                                               const float* __restrict__ b1,
                                               const float* __restrict__ w2,
                                               const float* __restrict__ b2) {
    __shared__ float pooled_s[256];
    __shared__ float hid_s[64];
    const int tid = threadIdx.x;
    {
        float s = 0.0f;
        const float* ps = &g_planesum[tid * 64];
        #pragma unroll 8
        for (int h = 0; h < 64; h++) s += ps[h];
        pooled_s[tid] = s * INV_N3;
    }
    __syncthreads();
    if (tid < 64) {
        const int b = tid >> 4, j = tid & 15;
        float acc = b1[j];
        #pragma unroll 8
        for (int c = 0; c < 64; c++) acc = fmaf(pooled_s[b * 64 + c], w1[c * 16 + j], acc);
        hid_s[tid] = fmaxf(acc, 0.0f);
    }
    __syncthreads();
    for (int j2 = tid; j2 < 4 * GATE_DIM; j2 += 256) {
        const int b = j2 / GATE_DIM, m = j2 % GATE_DIM;
        float acc = b2[m];
        #pragma unroll
        for (int j = 0; j < 16; j++) acc = fmaf(hid_s[b * 16 + j], w2[j * GATE_DIM + m], acc);
        float sig = 1.0f / (1.0f + expf(-acc));
        g_gate[j2] = (sig - 1.0f) * INV_N3;
    }
}

// ---------------------------------------------------------------------------
// Kernel 3: per (bc, 36-mode chunk): folded x-DFT -> gate -> folded x-inverse
// — identical to the 348us baseline
// ---------------------------------------------------------------------------
#define MCH 36
__global__ void __launch_bounds__(256) k_xstage() {
    __shared__ float2 Ys[64 * MCH];
    __shared__ float2 As[MCH * 17];
    __shared__ float2 tw[64];

    const int bx  = blockIdx.x;
    const int bc  = bx >> 2;
    const int b   = bc >> 6;
    const int m0  = (bx & 3) * MCH;
    const int tid = threadIdx.x;
    fill_tw(tw, tid);

    float2* Yg = &g_Y[(size_t)bc * 64 * NCOL];
    for (int j = tid; j < 64 * MCH; j += 256) {
        const int h = j / MCH, mL = j % MCH;
        Ys[j] = Yg[h * NCOL + m0 + mL];
    }
    __syncthreads();

    for (int j = tid; j < MCH * 16; j += 256) {
        const int kx = j / MCH;
        const int mL = j % MCH;
        const float sg = (kx & 1) ? -1.0f : 1.0f;
        float2 z0 = Ys[mL], z32 = Ys[32 * MCH + mL];
        float re = fmaf(sg, z32.x, z0.x);
        float im = fmaf(sg, z32.y, z0.y);
        #pragma unroll 31
        for (int hp = 1; hp <= 31; hp++) {
            float2 za = Ys[hp * MCH + mL];
            float2 zb = Ys[(64 - hp) * MCH + mL];
            float sx = za.x + zb.x, dxx = za.x - zb.x;
            float sy = za.y + zb.y, dy  = za.y - zb.y;
            float2 t = tw[(kx * hp) & 63];
            re = fmaf(sx, t.x, re); re = fmaf(dy, t.y, re);
            im = fmaf(sy, t.x, im); im = fmaf(-dxx, t.y, im);
        }
        float gate = g_gate[b * GATE_DIM + kx * NCOL + m0 + mL];
        As[mL * 17 + kx] = make_float2(re * gate, im * gate);
    }
    __syncthreads();

    for (int j = tid; j < 32 * MCH; j += 256) {
        const int hp = j / MCH;
        const int mL = j % MCH;
        float P = 0.f, Q = 0.f, R = 0.f, S = 0.f;
        #pragma unroll
        for (int kx = 0; kx < 16; kx++) {
            float2 A = As[mL * 17 + kx];
            float2 t = tw[(kx * hp) & 63];
            P = fmaf(A.x, t.x, P); Q = fmaf(A.y, t.y, Q);
            R = fmaf(A.y, t.x, R); S = fmaf(A.x, t.y, S);
        }
        if (hp == 0) {
            float P32 = 0.f, R32 = 0.f;
            #pragma unroll
            for (int kx = 0; kx < 16; kx++) {
                float2 A = As[mL * 17 + kx];
                float sg = (kx & 1) ? -1.0f : 1.0f;
                P32 = fmaf(A.x, sg, P32); R32 = fmaf(A.y, sg, R32);
            }
            Yg[m0 + mL]             = make_float2(P, R);
            Yg[32 * NCOL + m0 + mL] = make_float2(P32, R32);
        } else {
            Yg[hp * NCOL + m0 + mL]        = make_float2(P - Q, S + R);
            Yg[(64 - hp) * NCOL + m0 + mL] = make_float2(P + Q, R - S);
        }
    }
}

// ---------------------------------------------------------------------------
// Kernel 4: per-plane: folded y-inverse (R2 conflict-free layout), folded
// z-synthesis with PADDED B2s rows (80B) -> broadcast float4 loads.
// ---------------------------------------------------------------------------
__global__ void __launch_bounds__(256) k_inv(const float* __restrict__ x,
                                             float* __restrict__ out) {
    __shared__ float2 Yrow[NCOL];                    // [ky*9+kz], as in R2
    __shared__ __align__(16) float2 B2s[64 * 10];    // padded: 10 float2 per w
    __shared__ float2 tw[64];

    const int plane = blockIdx.x;
    const int tid   = threadIdx.x;
    fill_tw(tw, tid);
    if (tid < NCOL) Yrow[tid] = g_Y[(size_t)plane * NCOL + tid];
    __syncthreads();

    // Folded y-inverse: tasks 0..278 generic pairs, 279..287 w=0, 288..296 w=32
    for (int j = tid; j < 297; j += 256) {
        if (j < 279) {
            const int wp = j / 9 + 1;
            const int kz = j - (wp - 1) * 9;
            float rc = 0.f, rs = 0.f, ic = 0.f, is_ = 0.f;
            #pragma unroll
            for (int ky = 0; ky < 16; ky++) {
                float2 Yv = Yrow[ky * 9 + kz];
                float2 t  = tw[(ky * wp) & 63];
                rc = fmaf(Yv.x, t.x, rc); rs  = fmaf(Yv.y, t.y, rs);
                ic = fmaf(Yv.y, t.x, ic); is_ = fmaf(Yv.x, t.y, is_);
            }
            B2s[wp * 10 + kz]        = make_float2(rc - rs, is_ + ic);
            B2s[(64 - wp) * 10 + kz] = make_float2(rc + rs, ic - is_);
        } else if (j < 288) {
            const int kz = j - 279;                // w = 0: twiddle = 1
            float re = 0.f, im = 0.f;
            #pragma unroll
            for (int ky = 0; ky < 16; ky++) {
                float2 Yv = Yrow[ky * 9 + kz];
                re += Yv.x; im += Yv.y;
            }
            B2s[kz] = make_float2(re, im);
        } else {
            const int kz = j - 288;                // w = 32: twiddle = (-1)^ky
            float re = 0.f, im = 0.f;
            #pragma unroll
            for (int ky = 0; ky < 16; ky++) {
                float2 Yv = Yrow[ky * 9 + kz];
                float sg = (ky & 1) ? -1.0f : 1.0f;
                re = fmaf(Yv.x, sg, re); im = fmaf(Yv.y, sg, im);
            }
            B2s[32 * 10 + kz] = make_float2(re, im);
        }
    }
    __syncthreads();

    // Folded z-synthesis: lane dp handles d=dp and d=64-dp (dp=0 -> d=0 and 32)
    // w is warp-uniform -> all B2s loads are broadcast (conflict-free).
    const int dp = tid & 31;
    const int wg = tid >> 5;
    float cs[8], ss[8];
    #pragma unroll
    for (int kz = 1; kz <= 8; kz++) {
        float2 t = tw[(kz * dp) & 63];
        cs[kz - 1] = t.x; ss[kz - 1] = t.y;
    }
    const size_t base = (size_t)plane * 4096;
    const int d2 = (dp == 0) ? 32 : (64 - dp);
    #pragma unroll
    for (int k = 0; k < 8; k++) {
        const int w = wg * 8 + k;
        const float4* bp = (const float4*)&B2s[w * 10];   // 80B rows, 16B aligned
        float4 p0 = bp[0], p1 = bp[1], p2 = bp[2], p3 = bp[3];
        float2 p8 = B2s[w * 10 + 8];
        float Ac = 0.f, As2 = 0.f;
        Ac = fmaf(p0.z, cs[0], Ac); As2 = fmaf(p0.w, ss[0], As2);
        Ac = fmaf(p1.x, cs[1], Ac); As2 = fmaf(p1.y, ss[1], As2);
        Ac = fmaf(p1.z, cs[2], Ac); As2 = fmaf(p1.w, ss[2], As2);
        Ac = fmaf(p2.x, cs[3], Ac); As2 = fmaf(p2.y, ss[3], As2);
        Ac = fmaf(p2.z, cs[4], Ac); As2 = fmaf(p2.w, ss[4], As2);
        Ac = fmaf(p3.x, cs[5], Ac); As2 = fmaf(p3.y, ss[5], As2);
        Ac = fmaf(p3.z, cs[6], Ac); As2 = fmaf(p3.w, ss[6], As2);
        Ac = fmaf(p8.x, cs[7], Ac); As2 = fmaf(p8.y, ss[7], As2);
        const float b0 = p0.x;
        float v1 = fmaf(2.0f, Ac - As2, b0);
        float v2;
        if (dp == 0) {
            float A32 = (((p1.x - p0.z) + (p2.x - p1.z)) +
                         ((p3.x - p2.z) + (p8.x - p3.z)));
            v2 = fmaf(2.0f, A32, b0);
        } else {
            v2 = fmaf(2.0f, Ac + As2, b0);
        }
        const size_t i1 = base + (size_t)w * 64 + dp;
        const size_t i2 = base + (size_t)w * 64 + d2;
        out[i1] = x[i1] + v1;
        out[i2] = x[i2] + v2;
    }
}

// ---------------------------------------------------------------------------
extern "C" void kernel_launch(void* const* d_in, const int* in_sizes, int n_in,
                              void* d_out, int out_size) {
    const float* x  = (const float*)d_in[0];
    const float* w1 = (const float*)d_in[1];
    const float* b1 = (const float*)d_in[2];
    const float* w2 = (const float*)d_in[3];
    const float* b2 = (const float*)d_in[4];
    float* out = (float*)d_out;

    k_fwd<<<NPLANES, 256>>>(x);
    k_gates<<<1, 256>>>(w1, b1, w2, b2);
    k_xstage<<<1024, 256>>>();
    k_inv<<<NPLANES, 256>>>(x, out);
}

// round 10
// speedup vs baseline: 1.4838x; 1.0427x over previous
#include <cuda_runtime.h>
#include <math.h>

// x: [B=4, C=64, H=64, W=64, D=64] fp32
// out = x + irfftn(delta), delta = (gate-1)*rfftn(x) on corner [16,16,9]
#define NPLANES 16384   // B*C*H
#define GATE_DIM 2304   // 16*16*9
#define NCOL    144     // 16 ky * 9 kz

__device__ float2 g_Y[NPLANES * NCOL];     // 18.9 MB intermediate spectrum
__device__ float  g_planesum[NPLANES];
__device__ float  g_gate[4 * GATE_DIM];    // (sigmoid-1)/64^3

#define INV_N3 (1.0f / 262144.0f)

// Compile-time twiddles: TWC[t] = cos(2*pi*t/64); sin(t) = TWC[(t+48)&63]
__device__ constexpr float TWC[64] = {
     1.00000000f,  0.99518473f,  0.98078528f,  0.95694034f,
     0.92387953f,  0.88192126f,  0.83146961f,  0.77301045f,
     0.70710678f,  0.63439328f,  0.55557023f,  0.47139674f,
     0.38268343f,  0.29028468f,  0.19509032f,  0.09801714f,
     0.00000000f, -0.09801714f, -0.19509032f, -0.29028468f,
    -0.38268343f, -0.47139674f, -0.55557023f, -0.63439328f,
    -0.70710678f, -0.77301045f, -0.83146961f, -0.88192126f,
    -0.92387953f, -0.95694034f, -0.98078528f, -0.99518473f,
    -1.00000000f, -0.99518473f, -0.98078528f, -0.95694034f,
    -0.92387953f, -0.88192126f, -0.83146961f, -0.77301045f,
    -0.70710678f, -0.63439328f, -0.55557023f, -0.47139674f,
    -0.38268343f, -0.29028468f, -0.19509032f, -0.09801714f,
     0.00000000f,  0.09801714f,  0.19509032f,  0.29028468f,
     0.38268343f,  0.47139674f,  0.55557023f,  0.63439328f,
     0.70710678f,  0.77301045f,  0.83146961f,  0.88192126f,
     0.92387953f,  0.95694034f,  0.98078528f,  0.99518473f
};
__device__ __forceinline__ constexpr float twc(int t) { return TWC[t & 63]; }
__device__ __forceinline__ constexpr float tws(int t) { return TWC[(t + 48) & 63]; }

__device__ __forceinline__ void fill_tw(float2* tw, int tid) {
    if (tid < 64) {
        float s, c;
        sincospif((float)tid * (1.0f / 32.0f), &s, &c);
        tw[tid] = make_float2(c, s);
    }
}

// Folded z-DFT chunk: dp in [DP0, DP0+NDP), all 9 kz, compile-time twiddles.
template<int DP0, int NDP>
__device__ __forceinline__ void zchunk(const float* __restrict__ row,
                                       float* re, float* im) {
    #pragma unroll
    for (int i = 0; i < NDP; i++) {
        const int dp = DP0 + i;
        const float a = row[dp], b = row[64 - dp];
        const float e = a + b, o = a - b;
        re[0] += e;
        #pragma unroll
        for (int kz = 1; kz < 9; kz++) {
            re[kz] = fmaf(e, twc(kz * dp), re[kz]);
            im[kz] = fmaf(o, -tws(kz * dp), im[kz]);
        }
    }
}

// ---------------------------------------------------------------------------
// Kernel 1: per-plane: plane sum, z-DFT (immediate twiddles), folded y-DFT.
// ---------------------------------------------------------------------------
__global__ void __launch_bounds__(256) k_fwd(const float* __restrict__ x) {
    __shared__ __align__(16) float xs[64 * 65];   // [w][d] stride 65; reused as Zs
    __shared__ float2 Zpart[4 * 64 * 9];          // [q][w][kz]
    __shared__ float2 tw[64];
    __shared__ float  red[8];
    float2* Zs = (float2*)xs;

    const int plane = blockIdx.x;
    const int tid   = threadIdx.x;
    fill_tw(tw, tid);

    const float4* xp4 = (const float4*)(x + (size_t)plane * 4096);
    float psum = 0.0f;
    #pragma unroll
    for (int k = 0; k < 4; k++) {
        const int i4 = k * 256 + tid;
        float4 v = xp4[i4];
        const int base = i4 * 4;
        float* dst = &xs[(base >> 6) * 65 + (base & 63)];
        dst[0] = v.x; dst[1] = v.y; dst[2] = v.z; dst[3] = v.w;
        psum += (v.x + v.y) + (v.z + v.w);
    }
    #pragma unroll
    for (int o = 16; o > 0; o >>= 1) psum += __shfl_down_sync(0xffffffffu, psum, o);
    if ((tid & 31) == 0) red[tid >> 5] = psum;
    __syncthreads();
    if (tid == 0) {
        float s = 0.0f;
        #pragma unroll
        for (int i = 0; i < 8; i++) s += red[i];
        g_planesum[plane] = s;
    }

    {
        const int w = tid & 63;
        const int q = tid >> 6;
        float re[9], im[9];
        #pragma unroll
        for (int kz = 0; kz < 9; kz++) { re[kz] = 0.f; im[kz] = 0.f; }
        const float* row = &xs[w * 65];
        if (q == 0)      zchunk<1, 8>(row, re, im);
        else if (q == 1) zchunk<9, 8>(row, re, im);
        else if (q == 2) zchunk<17, 8>(row, re, im);
        else {
            zchunk<25, 7>(row, re, im);
            const float x0 = row[0], x32 = row[32];
            #pragma unroll
            for (int kz = 0; kz < 9; kz++)
                re[kz] += x0 + ((kz & 1) ? -x32 : x32);
        }
        float2* zp = &Zpart[(q * 64 + w) * 9];
        #pragma unroll
        for (int kz = 0; kz < 9; kz++) zp[kz] = make_float2(re[kz], im[kz]);
    }
    __syncthreads();

    for (int j = tid; j < 576; j += 256) {
        const int ww = j / 9, kz = j - ww * 9;
        float2 a = Zpart[ww * 9 + kz];
        float2 b = Zpart[(64 + ww) * 9 + kz];
        float2 c = Zpart[(128 + ww) * 9 + kz];
        float2 d = Zpart[(192 + ww) * 9 + kz];
        Zs[ww * 9 + kz] = make_float2((a.x + b.x) + (c.x + d.x),
                                      (a.y + b.y) + (c.y + d.y));
    }
    __syncthreads();

    if (tid < NCOL) {
        const int ky = tid / 9;
        const int kz = tid % 9;
        const float sg = (ky & 1) ? -1.0f : 1.0f;
        float2 z0 = Zs[kz], z32 = Zs[32 * 9 + kz];
        float re = fmaf(sg, z32.x, z0.x);
        float im = fmaf(sg, z32.y, z0.y);
        #pragma unroll 31
        for (int wp = 1; wp <= 31; wp++) {
            float2 za = Zs[wp * 9 + kz];
            float2 zb = Zs[(64 - wp) * 9 + kz];
            float sx = za.x + zb.x, dxx = za.x - zb.x;
            float sy = za.y + zb.y, dy  = za.y - zb.y;
            float2 t = tw[(ky * wp) & 63];
            re = fmaf(sx, t.x, re); re = fmaf(dy, t.y, re);
            im = fmaf(sy, t.x, im); im = fmaf(-dxx, t.y, im);
        }
        g_Y[(size_t)plane * NCOL + tid] = make_float2(re, im);
    }
}

// ---------------------------------------------------------------------------
// Kernel 2: gate MLP (single block)
// ---------------------------------------------------------------------------
__global__ void __launch_bounds__(256) k_gates(const float* __restrict__ w1,
                                               const float* __restrict__ b1,
                                               const float* __restrict__ w2,
                                               const float* __restrict__ b2) {
    __shared__ float pooled_s[256];
    __shared__ float hid_s[64];
    const int tid = threadIdx.x;
    {
        float s = 0.0f;
        const float* ps = &g_planesum[tid * 64];
        #pragma unroll 8
        for (int h = 0; h < 64; h++) s += ps[h];
        pooled_s[tid] = s * INV_N3;
    }
    __syncthreads();
    if (tid < 64) {
        const int b = tid >> 4, j = tid & 15;
        float acc = b1[j];
        #pragma unroll 8
        for (int c = 0; c < 64; c++) acc = fmaf(pooled_s[b * 64 + c], w1[c * 16 + j], acc);
        hid_s[tid] = fmaxf(acc, 0.0f);
    }
    __syncthreads();
    for (int j2 = tid; j2 < 4 * GATE_DIM; j2 += 256) {
        const int b = j2 / GATE_DIM, m = j2 % GATE_DIM;
        float acc = b2[m];
        #pragma unroll
        for (int j = 0; j < 16; j++) acc = fmaf(hid_s[b * 16 + j], w2[j * GATE_DIM + m], acc);
        float sig = 1.0f / (1.0f + expf(-acc));
        g_gate[j2] = (sig - 1.0f) * INV_N3;
    }
}

// ---------------------------------------------------------------------------
// Kernel 3: per (bc, 36-mode chunk): folded x-DFT -> gate -> folded x-inverse
// ---------------------------------------------------------------------------
#define MCH 36
__global__ void __launch_bounds__(256) k_xstage() {
    __shared__ float2 Ys[64 * MCH];
    __shared__ float2 As[MCH * 17];
    __shared__ float2 tw[64];

    const int bx  = blockIdx.x;
    const int bc  = bx >> 2;
    const int b   = bc >> 6;
    const int m0  = (bx & 3) * MCH;
    const int tid = threadIdx.x;
    fill_tw(tw, tid);

    float2* Yg = &g_Y[(size_t)bc * 64 * NCOL];
    for (int j = tid; j < 64 * MCH; j += 256) {
        const int h = j / MCH, mL = j % MCH;
        Ys[j] = Yg[h * NCOL + m0 + mL];
    }
    __syncthreads();

    for (int j = tid; j < MCH * 16; j += 256) {
        const int kx = j / MCH;
        const int mL = j % MCH;
        const float sg = (kx & 1) ? -1.0f : 1.0f;
        float2 z0 = Ys[mL], z32 = Ys[32 * MCH + mL];
        float re = fmaf(sg, z32.x, z0.x);
        float im = fmaf(sg, z32.y, z0.y);
        #pragma unroll 31
        for (int hp = 1; hp <= 31; hp++) {
            float2 za = Ys[hp * MCH + mL];
            float2 zb = Ys[(64 - hp) * MCH + mL];
            float sx = za.x + zb.x, dxx = za.x - zb.x;
            float sy = za.y + zb.y, dy  = za.y - zb.y;
            float2 t = tw[(kx * hp) & 63];
            re = fmaf(sx, t.x, re); re = fmaf(dy, t.y, re);
            im = fmaf(sy, t.x, im); im = fmaf(-dxx, t.y, im);
        }
        float gate = g_gate[b * GATE_DIM + kx * NCOL + m0 + mL];
        As[mL * 17 + kx] = make_float2(re * gate, im * gate);
    }
    __syncthreads();

    for (int j = tid; j < 32 * MCH; j += 256) {
        const int hp = j / MCH;
        const int mL = j % MCH;
        float P = 0.f, Q = 0.f, R = 0.f, S = 0.f;
        #pragma unroll
        for (int kx = 0; kx < 16; kx++) {
            float2 A = As[mL * 17 + kx];
            float2 t = tw[(kx * hp) & 63];
            P = fmaf(A.x, t.x, P); Q = fmaf(A.y, t.y, Q);
            R = fmaf(A.y, t.x, R); S = fmaf(A.x, t.y, S);
        }
        if (hp == 0) {
            float P32 = 0.f, R32 = 0.f;
            #pragma unroll
            for (int kx = 0; kx < 16; kx++) {
                float2 A = As[mL * 17 + kx];
                float sg = (kx & 1) ? -1.0f : 1.0f;
                P32 = fmaf(A.x, sg, P32); R32 = fmaf(A.y, sg, R32);
            }
            Yg[m0 + mL]             = make_float2(P, R);
            Yg[32 * NCOL + m0 + mL] = make_float2(P32, R32);
        } else {
            Yg[hp * NCOL + m0 + mL]        = make_float2(P - Q, S + R);
            Yg[(64 - hp) * NCOL + m0 + mL] = make_float2(P + Q, R - S);
        }
    }
}

// ---------------------------------------------------------------------------
// Kernel 4: per-plane: folded y-inverse (R2 layout), folded z-synthesis into
// smem delta buffer, then float4 epilogue: out4 = x4 + ds4.
// ---------------------------------------------------------------------------
__global__ void __launch_bounds__(256) k_inv(const float* __restrict__ x,
                                             float* __restrict__ out) {
    __shared__ float2 Yrow[NCOL];                  // [ky*9+kz]
    __shared__ float2 B2s[64 * 9];                 // [w][kz]
    __shared__ float2 tw[64];
    __shared__ __align__(16) float ds[4096];       // delta [w][d], stride 64

    const int plane = blockIdx.x;
    const int tid   = threadIdx.x;
    fill_tw(tw, tid);
    if (tid < NCOL) Yrow[tid] = g_Y[(size_t)plane * NCOL + tid];
    __syncthreads();

    // Folded y-inverse: tasks 0..278 generic pairs, 279..287 w=0, 288..296 w=32
    for (int j = tid; j < 297; j += 256) {
        if (j < 279) {
            const int wp = j / 9 + 1;
            const int kz = j - (wp - 1) * 9;
            float rc = 0.f, rs = 0.f, ic = 0.f, is_ = 0.f;
            #pragma unroll
            for (int ky = 0; ky < 16; ky++) {
                float2 Yv = Yrow[ky * 9 + kz];
                float2 t  = tw[(ky * wp) & 63];
                rc = fmaf(Yv.x, t.x, rc); rs  = fmaf(Yv.y, t.y, rs);
                ic = fmaf(Yv.y, t.x, ic); is_ = fmaf(Yv.x, t.y, is_);
            }
            B2s[wp * 9 + kz]        = make_float2(rc - rs, is_ + ic);
            B2s[(64 - wp) * 9 + kz] = make_float2(rc + rs, ic - is_);
        } else if (j < 288) {
            const int kz = j - 279;                // w = 0: twiddle = 1
            float re = 0.f, im = 0.f;
            #pragma unroll
            for (int ky = 0; ky < 16; ky++) {
                float2 Yv = Yrow[ky * 9 + kz];
                re += Yv.x; im += Yv.y;
            }
            B2s[kz] = make_float2(re, im);
        } else {
            const int kz = j - 288;                // w = 32: twiddle = (-1)^ky
            float re = 0.f, im = 0.f;
            #pragma unroll
            for (int ky = 0; ky < 16; ky++) {
                float2 Yv = Yrow[ky * 9 + kz];
                float sg = (ky & 1) ? -1.0f : 1.0f;
                re = fmaf(Yv.x, sg, re); im = fmaf(Yv.y, sg, im);
            }
            B2s[32 * 9 + kz] = make_float2(re, im);
        }
    }
    __syncthreads();

    // Folded z-synthesis -> ds (scalar STS, lane dp distinct -> conflict-free)
    {
        const int dp = tid & 31;
        const int wg = tid >> 5;              // w uniform per warp
        float cs[8], ss[8];
        #pragma unroll
        for (int kz = 1; kz <= 8; kz++) {
            float2 t = tw[(kz * dp) & 63];
            cs[kz - 1] = t.x; ss[kz - 1] = t.y;
        }
        const int d2 = (dp == 0) ? 32 : (64 - dp);
        #pragma unroll
        for (int k = 0; k < 8; k++) {
            const int w = wg * 8 + k;
            float2 Br[9];
            #pragma unroll
            for (int kz = 0; kz < 9; kz++) Br[kz] = B2s[w * 9 + kz];  // broadcast
            float Ac = 0.f, Asum = 0.f;
            #pragma unroll
            for (int kz = 1; kz <= 8; kz++) {
                Ac   = fmaf(Br[kz].x, cs[kz - 1], Ac);
                Asum = fmaf(Br[kz].y, ss[kz - 1], Asum);
            }
            const float b0 = Br[0].x;
            float v1 = fmaf(2.0f, Ac - Asum, b0);
            float v2 = fmaf(2.0f, Ac + Asum, b0);
            if (dp == 0) {
                float A32 = 0.f;
                #pragma unroll
                for (int kz = 1; kz <= 8; kz++) {
                    float sg = (kz & 1) ? -1.0f : 1.0f;
                    A32 = fmaf(Br[kz].x, sg, A32);
                }
                v2 = fmaf(2.0f, A32, b0);
            }
            ds[w * 64 + dp] = v1;
            ds[w * 64 + d2] = v2;
        }
    }
    __syncthreads();

    // Vectorized epilogue: out = x + delta, float4 all the way
    {
        const size_t base = (size_t)plane * 4096;
        const float4* xp4 = (const float4*)(x + base);
        float4*       op4 = (float4*)(out + base);
        const float4* dp4 = (const float4*)ds;
        #pragma unroll
        for (int k = 0; k < 4; k++) {
            const int i = k * 256 + tid;
            float4 xv = xp4[i];
            float4 dv = dp4[i];
            op4[i] = make_float4(xv.x + dv.x, xv.y + dv.y,
                                 xv.z + dv.z, xv.w + dv.w);
        }
    }
}

// ---------------------------------------------------------------------------
extern "C" void kernel_launch(void* const* d_in, const int* in_sizes, int n_in,
                              void* d_out, int out_size) {
    const float* x  = (const float*)d_in[0];
    const float* w1 = (const float*)d_in[1];
    const float* b1 = (const float*)d_in[2];
    const float* w2 = (const float*)d_in[3];
    const float* b2 = (const float*)d_in[4];
    float* out = (float*)d_out;

    k_fwd<<<NPLANES, 256>>>(x);
    k_gates<<<1, 256>>>(w1, b1, w2, b2);
    k_xstage<<<1024, 256>>>();
    k_inv<<<NPLANES, 256>>>(x, out);
}

// round 11
// speedup vs baseline: 1.5690x; 1.0575x over previous
#include <cuda_runtime.h>
#include <math.h>

// x: [B=4, C=64, H=64, W=64, D=64] fp32
// out = x + irfftn(delta), delta = (gate-1)*rfftn(x) on corner [16,16,9]
#define NPLANES 16384   // B*C*H
#define GATE_DIM 2304   // 16*16*9
#define NCOL    144     // 16 ky * 9 kz

__device__ float2 g_Y[NPLANES * NCOL];     // 18.9 MB intermediate spectrum
__device__ float  g_planesum[NPLANES];
__device__ float  g_gate[4 * GATE_DIM];    // (sigmoid-1)/64^3

#define INV_N3 (1.0f / 262144.0f)

// Compile-time twiddles: TWC[t] = cos(2*pi*t/64); sin(t) = TWC[(t+48)&63]
__device__ constexpr float TWC[64] = {
     1.00000000f,  0.99518473f,  0.98078528f,  0.95694034f,
     0.92387953f,  0.88192126f,  0.83146961f,  0.77301045f,
     0.70710678f,  0.63439328f,  0.55557023f,  0.47139674f,
     0.38268343f,  0.29028468f,  0.19509032f,  0.09801714f,
     0.00000000f, -0.09801714f, -0.19509032f, -0.29028468f,
    -0.38268343f, -0.47139674f, -0.55557023f, -0.63439328f,
    -0.70710678f, -0.77301045f, -0.83146961f, -0.88192126f,
    -0.92387953f, -0.95694034f, -0.98078528f, -0.99518473f,
    -1.00000000f, -0.99518473f, -0.98078528f, -0.95694034f,
    -0.92387953f, -0.88192126f, -0.83146961f, -0.77301045f,
    -0.70710678f, -0.63439328f, -0.55557023f, -0.47139674f,
    -0.38268343f, -0.29028468f, -0.19509032f, -0.09801714f,
     0.00000000f,  0.09801714f,  0.19509032f,  0.29028468f,
     0.38268343f,  0.47139674f,  0.55557023f,  0.63439328f,
     0.70710678f,  0.77301045f,  0.83146961f,  0.88192126f,
     0.92387953f,  0.95694034f,  0.98078528f,  0.99518473f
};
__device__ __forceinline__ constexpr float twc(int t) { return TWC[t & 63]; }
__device__ __forceinline__ constexpr float tws(int t) { return TWC[(t + 48) & 63]; }

__device__ __forceinline__ void fill_tw(float2* tw, int tid) {
    if (tid < 64) {
        float s, c;
        sincospif((float)tid * (1.0f / 32.0f), &s, &c);
        tw[tid] = make_float2(c, s);
    }
}

// Advance complex rotation (tc, ts) by step (sx, sy): t *= s
#define ROT_ADV(tc, ts, sx, sy) do {                 \
    float _p = (ts) * (sy);                          \
    float _n = fmaf((tc), (sx), -_p);                \
    (ts) = fmaf((tc), (sy), (ts) * (sx));            \
    (tc) = _n;                                       \
} while (0)

// Folded z-DFT chunk: dp in [DP0, DP0+NDP), all 9 kz, compile-time twiddles.
template<int DP0, int NDP>
__device__ __forceinline__ void zchunk(const float* __restrict__ row,
                                       float* re, float* im) {
    #pragma unroll
    for (int i = 0; i < NDP; i++) {
        const int dp = DP0 + i;
        const float a = row[dp], b = row[64 - dp];
        const float e = a + b, o = a - b;
        re[0] += e;
        #pragma unroll
        for (int kz = 1; kz < 9; kz++) {
            re[kz] = fmaf(e, twc(kz * dp), re[kz]);
            im[kz] = fmaf(o, -tws(kz * dp), im[kz]);
        }
    }
}

// ---------------------------------------------------------------------------
// Kernel 1: per-plane: plane sum, z-DFT (immediate twiddles), y-DFT with
// twiddle recurrence (removes 1 LDS per inner iteration).
// ---------------------------------------------------------------------------
__global__ void __launch_bounds__(256) k_fwd(const float* __restrict__ x) {
    __shared__ __align__(16) float xs[64 * 65];   // [w][d] stride 65; reused as Zs
    __shared__ float2 Zpart[4 * 64 * 9];          // [q][w][kz]
    __shared__ float2 tw[64];
    __shared__ float  red[8];
    float2* Zs = (float2*)xs;

    const int plane = blockIdx.x;
    const int tid   = threadIdx.x;
    fill_tw(tw, tid);

    const float4* xp4 = (const float4*)(x + (size_t)plane * 4096);
    float psum = 0.0f;
    #pragma unroll
    for (int k = 0; k < 4; k++) {
        const int i4 = k * 256 + tid;
        float4 v = xp4[i4];
        const int base = i4 * 4;
        float* dst = &xs[(base >> 6) * 65 + (base & 63)];
        dst[0] = v.x; dst[1] = v.y; dst[2] = v.z; dst[3] = v.w;
        psum += (v.x + v.y) + (v.z + v.w);
    }
    #pragma unroll
    for (int o = 16; o > 0; o >>= 1) psum += __shfl_down_sync(0xffffffffu, psum, o);
    if ((tid & 31) == 0) red[tid >> 5] = psum;
    __syncthreads();
    if (tid == 0) {
        float s = 0.0f;
        #pragma unroll
        for (int i = 0; i < 8; i++) s += red[i];
        g_planesum[plane] = s;
    }

    {
        const int w = tid & 63;
        const int q = tid >> 6;
        float re[9], im[9];
        #pragma unroll
        for (int kz = 0; kz < 9; kz++) { re[kz] = 0.f; im[kz] = 0.f; }
        const float* row = &xs[w * 65];
        if (q == 0)      zchunk<1, 8>(row, re, im);
        else if (q == 1) zchunk<9, 8>(row, re, im);
        else if (q == 2) zchunk<17, 8>(row, re, im);
        else {
            zchunk<25, 7>(row, re, im);
            const float x0 = row[0], x32 = row[32];
            #pragma unroll
            for (int kz = 0; kz < 9; kz++)
                re[kz] += x0 + ((kz & 1) ? -x32 : x32);
        }
        float2* zp = &Zpart[(q * 64 + w) * 9];
        #pragma unroll
        for (int kz = 0; kz < 9; kz++) zp[kz] = make_float2(re[kz], im[kz]);
    }
    __syncthreads();

    for (int j = tid; j < 576; j += 256) {
        const int ww = j / 9, kz = j - ww * 9;
        float2 a = Zpart[ww * 9 + kz];
        float2 b = Zpart[(64 + ww) * 9 + kz];
        float2 c = Zpart[(128 + ww) * 9 + kz];
        float2 d = Zpart[(192 + ww) * 9 + kz];
        Zs[ww * 9 + kz] = make_float2((a.x + b.x) + (c.x + d.x),
                                      (a.y + b.y) + (c.y + d.y));
    }
    __syncthreads();

    if (tid < NCOL) {
        const int ky = tid / 9;
        const int kz = tid % 9;
        const float sg = (ky & 1) ? -1.0f : 1.0f;
        float2 z0 = Zs[kz], z32 = Zs[32 * 9 + kz];
        float re = fmaf(sg, z32.x, z0.x);
        float im = fmaf(sg, z32.y, z0.y);
        const float2 st = tw[ky];        // step: angle ky per wp
        float tc = st.x, ts = st.y;      // twiddle for wp = 1
        #pragma unroll 31
        for (int wp = 1; wp <= 31; wp++) {
            float2 za = Zs[wp * 9 + kz];
            float2 zb = Zs[(64 - wp) * 9 + kz];
            float sx = za.x + zb.x, dxx = za.x - zb.x;
            float sy = za.y + zb.y, dy  = za.y - zb.y;
            re = fmaf(sx, tc, re); re = fmaf(dy, ts, re);
            im = fmaf(sy, tc, im); im = fmaf(-dxx, ts, im);
            ROT_ADV(tc, ts, st.x, st.y);
        }
        g_Y[(size_t)plane * NCOL + tid] = make_float2(re, im);
    }
}

// ---------------------------------------------------------------------------
// Kernel 2: gate MLP (single block)
// ---------------------------------------------------------------------------
__global__ void __launch_bounds__(256) k_gates(const float* __restrict__ w1,
                                               const float* __restrict__ b1,
                                               const float* __restrict__ w2,
                                               const float* __restrict__ b2) {
    __shared__ float pooled_s[256];
    __shared__ float hid_s[64];
    const int tid = threadIdx.x;
    {
        float s = 0.0f;
        const float* ps = &g_planesum[tid * 64];
        #pragma unroll 8
        for (int h = 0; h < 64; h++) s += ps[h];
        pooled_s[tid] = s * INV_N3;
    }
    __syncthreads();
    if (tid < 64) {
        const int b = tid >> 4, j = tid & 15;
        float acc = b1[j];
        #pragma unroll 8
        for (int c = 0; c < 64; c++) acc = fmaf(pooled_s[b * 64 + c], w1[c * 16 + j], acc);
        hid_s[tid] = fmaxf(acc, 0.0f);
    }
    __syncthreads();
    for (int j2 = tid; j2 < 4 * GATE_DIM; j2 += 256) {
        const int b = j2 / GATE_DIM, m = j2 % GATE_DIM;
        float acc = b2[m];
        #pragma unroll
        for (int j = 0; j < 16; j++) acc = fmaf(hid_s[b * 16 + j], w2[j * GATE_DIM + m], acc);
        float sig = 1.0f / (1.0f + expf(-acc));
        g_gate[j2] = (sig - 1.0f) * INV_N3;
    }
}

// ---------------------------------------------------------------------------
// Kernel 3: per (bc, 36-mode chunk): folded x-DFT -> gate -> folded x-inverse
// with twiddle recurrences in both phases.
// ---------------------------------------------------------------------------
#define MCH 36
__global__ void __launch_bounds__(256) k_xstage() {
    __shared__ float2 Ys[64 * MCH];
    __shared__ float2 As[MCH * 17];
    __shared__ float2 tw[64];

    const int bx  = blockIdx.x;
    const int bc  = bx >> 2;
    const int b   = bc >> 6;
    const int m0  = (bx & 3) * MCH;
    const int tid = threadIdx.x;
    fill_tw(tw, tid);

    float2* Yg = &g_Y[(size_t)bc * 64 * NCOL];
    for (int j = tid; j < 64 * MCH; j += 256) {
        const int h = j / MCH, mL = j % MCH;
        Ys[j] = Yg[h * NCOL + m0 + mL];
    }
    __syncthreads();

    for (int j = tid; j < MCH * 16; j += 256) {
        const int kx = j / MCH;
        const int mL = j % MCH;
        const float sg = (kx & 1) ? -1.0f : 1.0f;
        float2 z0 = Ys[mL], z32 = Ys[32 * MCH + mL];
        float re = fmaf(sg, z32.x, z0.x);
        float im = fmaf(sg, z32.y, z0.y);
        const float2 st = tw[kx];       // step per hp
        float tc = st.x, ts = st.y;     // twiddle for hp = 1
        #pragma unroll 31
        for (int hp = 1; hp <= 31; hp++) {
            float2 za = Ys[hp * MCH + mL];
            float2 zb = Ys[(64 - hp) * MCH + mL];
            float sx = za.x + zb.x, dxx = za.x - zb.x;
            float sy = za.y + zb.y, dy  = za.y - zb.y;
            re = fmaf(sx, tc, re); re = fmaf(dy, ts, re);
            im = fmaf(sy, tc, im); im = fmaf(-dxx, ts, im);
            ROT_ADV(tc, ts, st.x, st.y);
        }
        float gate = g_gate[b * GATE_DIM + kx * NCOL + m0 + mL];
        As[mL * 17 + kx] = make_float2(re * gate, im * gate);
    }
    __syncthreads();

    for (int j = tid; j < 32 * MCH; j += 256) {
        const int hp = j / MCH;
        const int mL = j % MCH;
        float P = 0.f, Q = 0.f, R = 0.f, S = 0.f;
        const float2 st = tw[hp];       // step per kx
        float tc = 1.f, ts = 0.f;       // twiddle for kx = 0
        #pragma unroll
        for (int kx = 0; kx < 16; kx++) {
            float2 A = As[mL * 17 + kx];
            P = fmaf(A.x, tc, P); Q = fmaf(A.y, ts, Q);
            R = fmaf(A.y, tc, R); S = fmaf(A.x, ts, S);
            ROT_ADV(tc, ts, st.x, st.y);
        }
        if (hp == 0) {
            float P32 = 0.f, R32 = 0.f;
            #pragma unroll
            for (int kx = 0; kx < 16; kx++) {
                float2 A = As[mL * 17 + kx];
                float sg = (kx & 1) ? -1.0f : 1.0f;
                P32 = fmaf(A.x, sg, P32); R32 = fmaf(A.y, sg, R32);
            }
            Yg[m0 + mL]             = make_float2(P, R);
            Yg[32 * NCOL + m0 + mL] = make_float2(P32, R32);
        } else {
            Yg[hp * NCOL + m0 + mL]        = make_float2(P - Q, S + R);
            Yg[(64 - hp) * NCOL + m0 + mL] = make_float2(P + Q, R - S);
        }
    }
}

// ---------------------------------------------------------------------------
// Kernel 4: per-plane: y-inverse (twiddle recurrence) -> padded B2s ->
// z-synthesis (float4 broadcast Br loads) -> direct scalar out = x + delta.
// ---------------------------------------------------------------------------
__global__ void __launch_bounds__(256) k_inv(const float* __restrict__ x,
                                             float* __restrict__ out) {
    __shared__ float2 Yrow[NCOL];                    // [ky*9+kz]
    __shared__ __align__(16) float2 B2s[64 * 10];    // padded rows: 80B
    __shared__ float2 tw[64];

    const int plane = blockIdx.x;
    const int tid   = threadIdx.x;
    fill_tw(tw, tid);
    if (tid < NCOL) Yrow[tid] = g_Y[(size_t)plane * NCOL + tid];
    __syncthreads();

    // Folded y-inverse: tasks 0..278 generic pairs, 279..287 w=0, 288..296 w=32
    for (int j = tid; j < 297; j += 256) {
        if (j < 279) {
            const int wp = j / 9 + 1;
            const int kz = j - (wp - 1) * 9;
            const float2 st = tw[wp];       // step per ky
            float2 Y0 = Yrow[kz];
            float rc = Y0.x, rs = 0.f, ic = Y0.y, is_ = 0.f;
            float tc = st.x, ts = st.y;     // twiddle for ky = 1
            #pragma unroll 15
            for (int ky = 1; ky < 16; ky++) {
                float2 Yv = Yrow[ky * 9 + kz];
                rc = fmaf(Yv.x, tc, rc); rs  = fmaf(Yv.y, ts, rs);
                ic = fmaf(Yv.y, tc, ic); is_ = fmaf(Yv.x, ts, is_);
                ROT_ADV(tc, ts, st.x, st.y);
            }
            B2s[wp * 10 + kz]        = make_float2(rc - rs, is_ + ic);
            B2s[(64 - wp) * 10 + kz] = make_float2(rc + rs, ic - is_);
        } else if (j < 288) {
            const int kz = j - 279;                // w = 0: twiddle = 1
            float re = 0.f, im = 0.f;
            #pragma unroll
            for (int ky = 0; ky < 16; ky++) {
                float2 Yv = Yrow[ky * 9 + kz];
                re += Yv.x; im += Yv.y;
            }
            B2s[kz] = make_float2(re, im);
        } else {
            const int kz = j - 288;                // w = 32: twiddle = (-1)^ky
            float re = 0.f, im = 0.f;
            #pragma unroll
            for (int ky = 0; ky < 16; ky++) {
                float2 Yv = Yrow[ky * 9 + kz];
                float sg = (ky & 1) ? -1.0f : 1.0f;
                re = fmaf(Yv.x, sg, re); im = fmaf(Yv.y, sg, im);
            }
            B2s[32 * 10 + kz] = make_float2(re, im);
        }
    }
    __syncthreads();

    // Folded z-synthesis: lane dp handles d=dp and d=64-dp (dp=0 -> d=0, 32).
    // cs/ss built by recurrence (no LDS); Br rows read as broadcast float4.
    const int dp = tid & 31;
    const int wg = tid >> 5;
    float cs[8], ss[8];
    {
        const float2 st = tw[dp];
        float tc = st.x, ts = st.y;     // angle dp (kz=1)
        #pragma unroll
        for (int kz = 1; kz <= 8; kz++) {
            cs[kz - 1] = tc; ss[kz - 1] = ts;
            ROT_ADV(tc, ts, st.x, st.y);
        }
    }
    const size_t base = (size_t)plane * 4096;
    const int d2 = (dp == 0) ? 32 : (64 - dp);
    #pragma unroll
    for (int k = 0; k < 8; k++) {
        const int w = wg * 8 + k;
        const float4* bp = (const float4*)&B2s[w * 10];   // broadcast
        float4 q0 = bp[0], q1 = bp[1], q2 = bp[2], q3 = bp[3];
        float2 q4 = B2s[w * 10 + 8];
        float Ac  = q0.z * cs[0];
        float As2 = q0.w * ss[0];
        Ac = fmaf(q1.x, cs[1], Ac); As2 = fmaf(q1.y, ss[1], As2);
        Ac = fmaf(q1.z, cs[2], Ac); As2 = fmaf(q1.w, ss[2], As2);
        Ac = fmaf(q2.x, cs[3], Ac); As2 = fmaf(q2.y, ss[3], As2);
        Ac = fmaf(q2.z, cs[4], Ac); As2 = fmaf(q2.w, ss[4], As2);
        Ac = fmaf(q3.x, cs[5], Ac); As2 = fmaf(q3.y, ss[5], As2);
        Ac = fmaf(q3.z, cs[6], Ac); As2 = fmaf(q3.w, ss[6], As2);
        Ac = fmaf(q4.x, cs[7], Ac); As2 = fmaf(q4.y, ss[7], As2);
        const float b0 = q0.x;
        float v1 = fmaf(2.0f, Ac - As2, b0);
        float v2;
        if (dp == 0) {
            float A32 = ((q1.x - q0.z) + (q2.x - q1.z)) +
                        ((q3.x - q2.z) + (q4.x - q3.z));
            v2 = fmaf(2.0f, A32, b0);
        } else {
            v2 = fmaf(2.0f, Ac + As2, b0);
        }
        const size_t i1 = base + (size_t)w * 64 + dp;
        const size_t i2 = base + (size_t)w * 64 + d2;
        out[i1] = x[i1] + v1;
        out[i2] = x[i2] + v2;
    }
}

// ---------------------------------------------------------------------------
extern "C" void kernel_launch(void* const* d_in, const int* in_sizes, int n_in,
                              void* d_out, int out_size) {
    const float* x  = (const float*)d_in[0];
    const float* w1 = (const float*)d_in[1];
    const float* b1 = (const float*)d_in[2];
    const float* w2 = (const float*)d_in[3];
    const float* b2 = (const float*)d_in[4];
    float* out = (float*)d_out;

    k_fwd<<<NPLANES, 256>>>(x);
    k_gates<<<1, 256>>>(w1, b1, w2, b2);
    k_xstage<<<1024, 256>>>();
    k_inv<<<NPLANES, 256>>>(x, out);
}

// round 14
// speedup vs baseline: 1.6303x; 1.0391x over previous
#include <cuda_runtime.h>
#include <math.h>

// x: [B=4, C=64, H=64, W=64, D=64] fp32
// out = x + irfftn(delta), delta = (gate-1)*rfftn(x) on corner [16,16,9]
#define NPLANES 16384   // B*C*H
#define GATE_DIM 2304   // 16*16*9
#define NCOL    144     // 16 ky * 9 kz

__device__ float2 g_Y[NPLANES * NCOL];     // 18.9 MB intermediate spectrum
__device__ float  g_planesum[NPLANES];
__device__ float  g_gate[4 * GATE_DIM];    // (sigmoid-1)/64^3

#define INV_N3 (1.0f / 262144.0f)

// Compile-time twiddles: TWC[t] = cos(2*pi*t/64); sin(t) = TWC[(t+48)&63]
__device__ constexpr float TWC[64] = {
     1.00000000f,  0.99518473f,  0.98078528f,  0.95694034f,
     0.92387953f,  0.88192126f,  0.83146961f,  0.77301045f,
     0.70710678f,  0.63439328f,  0.55557023f,  0.47139674f,
     0.38268343f,  0.29028468f,  0.19509032f,  0.09801714f,
     0.00000000f, -0.09801714f, -0.19509032f, -0.29028468f,
    -0.38268343f, -0.47139674f, -0.55557023f, -0.63439328f,
    -0.70710678f, -0.77301045f, -0.83146961f, -0.88192126f,
    -0.92387953f, -0.95694034f, -0.98078528f, -0.99518473f,
    -1.00000000f, -0.99518473f, -0.98078528f, -0.95694034f,
    -0.92387953f, -0.88192126f, -0.83146961f, -0.77301045f,
    -0.70710678f, -0.63439328f, -0.55557023f, -0.47139674f,
    -0.38268343f, -0.29028468f, -0.19509032f, -0.09801714f,
     0.00000000f,  0.09801714f,  0.19509032f,  0.29028468f,
     0.38268343f,  0.47139674f,  0.55557023f,  0.63439328f,
     0.70710678f,  0.77301045f,  0.83146961f,  0.88192126f,
     0.92387953f,  0.95694034f,  0.98078528f,  0.99518473f
};
__device__ __forceinline__ constexpr float twc(int t) { return TWC[t & 63]; }
__device__ __forceinline__ constexpr float tws(int t) { return TWC[(t + 48) & 63]; }

__device__ __forceinline__ void fill_tw(float2* tw, int tid) {
    if (tid < 64) {
        float s, c;
        sincospif((float)tid * (1.0f / 32.0f), &s, &c);
        tw[tid] = make_float2(c, s);
    }
}

// Advance complex rotation (tc, ts) by step (sx, sy): t *= s
#define ROT_ADV(tc, ts, sx, sy) do {                 \
    float _p = (ts) * (sy);                          \
    float _n = fmaf((tc), (sx), -_p);                \
    (ts) = fmaf((tc), (sy), (ts) * (sx));            \
    (tc) = _n;                                       \
} while (0)

// Folded z-DFT chunk: dp in [DP0, DP0+NDP), all 9 kz, compile-time twiddles.
template<int DP0, int NDP>
__device__ __forceinline__ void zchunk(const float* __restrict__ row,
                                       float* re, float* im) {
    #pragma unroll
    for (int i = 0; i < NDP; i++) {
        const int dp = DP0 + i;
        const float a = row[dp], b = row[64 - dp];
        const float e = a + b, o = a - b;
        re[0] += e;
        #pragma unroll
        for (int kz = 1; kz < 9; kz++) {
            re[kz] = fmaf(e, twc(kz * dp), re[kz]);
            im[kz] = fmaf(o, -tws(kz * dp), im[kz]);
        }
    }
}

// ---------------------------------------------------------------------------
// Kernel 1: per-plane: plane sum, z-DFT (immediate twiddles), y-DFT with
// twiddle recurrence.
// ---------------------------------------------------------------------------
__global__ void __launch_bounds__(256) k_fwd(const float* __restrict__ x) {
    __shared__ __align__(16) float xs[64 * 65];   // [w][d] stride 65; reused as Zs
    __shared__ float2 Zpart[4 * 64 * 9];          // [q][w][kz]
    __shared__ float2 tw[64];
    __shared__ float  red[8];
    float2* Zs = (float2*)xs;

    const int plane = blockIdx.x;
    const int tid   = threadIdx.x;
    fill_tw(tw, tid);

    const float4* xp4 = (const float4*)(x + (size_t)plane * 4096);
    float psum = 0.0f;
    #pragma unroll
    for (int k = 0; k < 4; k++) {
        const int i4 = k * 256 + tid;
        float4 v = xp4[i4];
        const int base = i4 * 4;
        float* dst = &xs[(base >> 6) * 65 + (base & 63)];
        dst[0] = v.x; dst[1] = v.y; dst[2] = v.z; dst[3] = v.w;
        psum += (v.x + v.y) + (v.z + v.w);
    }
    #pragma unroll
    for (int o = 16; o > 0; o >>= 1) psum += __shfl_down_sync(0xffffffffu, psum, o);
    if ((tid & 31) == 0) red[tid >> 5] = psum;
    __syncthreads();
    if (tid == 0) {
        float s = 0.0f;
        #pragma unroll
        for (int i = 0; i < 8; i++) s += red[i];
        g_planesum[plane] = s;
    }

    {
        const int w = tid & 63;
        const int q = tid >> 6;
        float re[9], im[9];
        #pragma unroll
        for (int kz = 0; kz < 9; kz++) { re[kz] = 0.f; im[kz] = 0.f; }
        const float* row = &xs[w * 65];
        if (q == 0)      zchunk<1, 8>(row, re, im);
        else if (q == 1) zchunk<9, 8>(row, re, im);
        else if (q == 2) zchunk<17, 8>(row, re, im);
        else {
            zchunk<25, 7>(row, re, im);
            const float x0 = row[0], x32 = row[32];
            #pragma unroll
            for (int kz = 0; kz < 9; kz++)
                re[kz] += x0 + ((kz & 1) ? -x32 : x32);
        }
        float2* zp = &Zpart[(q * 64 + w) * 9];
        #pragma unroll
        for (int kz = 0; kz < 9; kz++) zp[kz] = make_float2(re[kz], im[kz]);
    }
    __syncthreads();

    for (int j = tid; j < 576; j += 256) {
        const int ww = j / 9, kz = j - ww * 9;
        float2 a = Zpart[ww * 9 + kz];
        float2 b = Zpart[(64 + ww) * 9 + kz];
        float2 c = Zpart[(128 + ww) * 9 + kz];
        float2 d = Zpart[(192 + ww) * 9 + kz];
        Zs[ww * 9 + kz] = make_float2((a.x + b.x) + (c.x + d.x),
                                      (a.y + b.y) + (c.y + d.y));
    }
    __syncthreads();

    if (tid < NCOL) {
        const int ky = tid / 9;
        const int kz = tid % 9;
        const float sg = (ky & 1) ? -1.0f : 1.0f;
        float2 z0 = Zs[kz], z32 = Zs[32 * 9 + kz];
        float re = fmaf(sg, z32.x, z0.x);
        float im = fmaf(sg, z32.y, z0.y);
        const float2 st = tw[ky];        // step: angle ky per wp
        float tc = st.x, ts = st.y;      // twiddle for wp = 1
        #pragma unroll 31
        for (int wp = 1; wp <= 31; wp++) {
            float2 za = Zs[wp * 9 + kz];
            float2 zb = Zs[(64 - wp) * 9 + kz];
            float sx = za.x + zb.x, dxx = za.x - zb.x;
            float sy = za.y + zb.y, dy  = za.y - zb.y;
            re = fmaf(sx, tc, re); re = fmaf(dy, ts, re);
            im = fmaf(sy, tc, im); im = fmaf(-dxx, ts, im);
            ROT_ADV(tc, ts, st.x, st.y);
        }
        g_Y[(size_t)plane * NCOL + tid] = make_float2(re, im);
    }
}

// ---------------------------------------------------------------------------
// Kernel 2: gate MLP (single block)
// ---------------------------------------------------------------------------
__global__ void __launch_bounds__(256) k_gates(const float* __restrict__ w1,
                                               const float* __restrict__ b1,
                                               const float* __restrict__ w2,
                                               const float* __restrict__ b2) {
    __shared__ float pooled_s[256];
    __shared__ float hid_s[64];
    const int tid = threadIdx.x;
    {
        float s = 0.0f;
        const float* ps = &g_planesum[tid * 64];
        #pragma unroll 8
        for (int h = 0; h < 64; h++) s += ps[h];
        pooled_s[tid] = s * INV_N3;
    }
    __syncthreads();
    if (tid < 64) {
        const int b = tid >> 4, j = tid & 15;
        float acc = b1[j];
        #pragma unroll 8
        for (int c = 0; c < 64; c++) acc = fmaf(pooled_s[b * 64 + c], w1[c * 16 + j], acc);
        hid_s[tid] = fmaxf(acc, 0.0f);
    }
    __syncthreads();
    for (int j2 = tid; j2 < 4 * GATE_DIM; j2 += 256) {
        const int b = j2 / GATE_DIM, m = j2 % GATE_DIM;
        float acc = b2[m];
        #pragma unroll
        for (int j = 0; j < 16; j++) acc = fmaf(hid_s[b * 16 + j], w2[j * GATE_DIM + m], acc);
        float sig = 1.0f / (1.0f + expf(-acc));
        g_gate[j2] = (sig - 1.0f) * INV_N3;
    }
}

// ---------------------------------------------------------------------------
// Kernel 3: per (bc, 36-mode chunk): folded x-DFT -> gate -> folded x-inverse
// with twiddle recurrences in both phases.
// ---------------------------------------------------------------------------
#define MCH 36
__global__ void __launch_bounds__(256) k_xstage() {
    __shared__ float2 Ys[64 * MCH];
    __shared__ float2 As[MCH * 17];
    __shared__ float2 tw[64];

    const int bx  = blockIdx.x;
    const int bc  = bx >> 2;
    const int b   = bc >> 6;
    const int m0  = (bx & 3) * MCH;
    const int tid = threadIdx.x;
    fill_tw(tw, tid);

    float2* Yg = &g_Y[(size_t)bc * 64 * NCOL];
    for (int j = tid; j < 64 * MCH; j += 256) {
        const int h = j / MCH, mL = j % MCH;
        Ys[j] = Yg[h * NCOL + m0 + mL];
    }
    __syncthreads();

    for (int j = tid; j < MCH * 16; j += 256) {
        const int kx = j / MCH;
        const int mL = j % MCH;
        const float sg = (kx & 1) ? -1.0f : 1.0f;
        float2 z0 = Ys[mL], z32 = Ys[32 * MCH + mL];
        float re = fmaf(sg, z32.x, z0.x);
        float im = fmaf(sg, z32.y, z0.y);
        const float2 st = tw[kx];       // step per hp
        float tc = st.x, ts = st.y;     // twiddle for hp = 1
        #pragma unroll 31
        for (int hp = 1; hp <= 31; hp++) {
            float2 za = Ys[hp * MCH + mL];
            float2 zb = Ys[(64 - hp) * MCH + mL];
            float sx = za.x + zb.x, dxx = za.x - zb.x;
            float sy = za.y + zb.y, dy  = za.y - zb.y;
            re = fmaf(sx, tc, re); re = fmaf(dy, ts, re);
            im = fmaf(sy, tc, im); im = fmaf(-dxx, ts, im);
            ROT_ADV(tc, ts, st.x, st.y);
        }
        float gate = g_gate[b * GATE_DIM + kx * NCOL + m0 + mL];
        As[mL * 17 + kx] = make_float2(re * gate, im * gate);
    }
    __syncthreads();

    for (int j = tid; j < 32 * MCH; j += 256) {
        const int hp = j / MCH;
        const int mL = j % MCH;
        float P = 0.f, Q = 0.f, R = 0.f, S = 0.f;
        const float2 st = tw[hp];       // step per kx
        float tc = 1.f, ts = 0.f;       // twiddle for kx = 0
        #pragma unroll
        for (int kx = 0; kx < 16; kx++) {
            float2 A = As[mL * 17 + kx];
            P = fmaf(A.x, tc, P); Q = fmaf(A.y, ts, Q);
            R = fmaf(A.y, tc, R); S = fmaf(A.x, ts, S);
            ROT_ADV(tc, ts, st.x, st.y);
        }
        if (hp == 0) {
            float P32 = 0.f, R32 = 0.f;
            #pragma unroll
            for (int kx = 0; kx < 16; kx++) {
                float2 A = As[mL * 17 + kx];
                float sg = (kx & 1) ? -1.0f : 1.0f;
                P32 = fmaf(A.x, sg, P32); R32 = fmaf(A.y, sg, R32);
            }
            Yg[m0 + mL]             = make_float2(P, R);
            Yg[32 * NCOL + m0 + mL] = make_float2(P32, R32);
        } else {
            Yg[hp * NCOL + m0 + mL]        = make_float2(P - Q, S + R);
            Yg[(64 - hp) * NCOL + m0 + mL] = make_float2(P + Q, R - S);
        }
    }
}

// ---------------------------------------------------------------------------
// Kernel 4: per-plane: y-inverse (twiddle recurrence) -> B2s[w][kz] ->
// direct z-synthesis via smem cos/sin tables, float4 global I/O.
// ---------------------------------------------------------------------------
__global__ void __launch_bounds__(256) k_inv(const float* __restrict__ x,
                                             float* __restrict__ out) {
    __shared__ float2 Yrow[NCOL];                 // [ky*9+kz]
    __shared__ float2 B2s[64 * 9];                // [w][kz], stride 9
    __shared__ float2 tw[64];
    __shared__ __align__(16) float Csyn[8 * 64];  // [kz-1][d]
    __shared__ __align__(16) float Ssyn[8 * 64];

    const int plane = blockIdx.x;
    const int tid   = threadIdx.x;
    fill_tw(tw, tid);

    // Build synthesis tables: Csyn[kz-1][d] = cos(2pi kz d/64), Ssyn = sin
    for (int e = tid; e < 512; e += 256) {
        const int kz = (e >> 6) + 1;
        const int d  = e & 63;
        float s, c;
        sincospif((float)((kz * d) & 63) * (1.0f / 32.0f), &s, &c);
        Csyn[e] = c; Ssyn[e] = s;
    }
    if (tid < NCOL) Yrow[tid] = g_Y[(size_t)plane * NCOL + tid];
    __syncthreads();

    // Folded y-inverse: tasks 0..278 generic pairs, 279..287 w=0, 288..296 w=32
    for (int j = tid; j < 297; j += 256) {
        if (j < 279) {
            const int wp = j / 9 + 1;
            const int kz = j - (wp - 1) * 9;
            const float2 st = tw[wp];       // step per ky
            float2 Y0 = Yrow[kz];
            float rc = Y0.x, rs = 0.f, ic = Y0.y, is_ = 0.f;
            float tc = st.x, ts = st.y;     // twiddle for ky = 1
            #pragma unroll 15
            for (int ky = 1; ky < 16; ky++) {
                float2 Yv = Yrow[ky * 9 + kz];
                rc = fmaf(Yv.x, tc, rc); rs  = fmaf(Yv.y, ts, rs);
                ic = fmaf(Yv.y, tc, ic); is_ = fmaf(Yv.x, ts, is_);
                ROT_ADV(tc, ts, st.x, st.y);
            }
            B2s[wp * 9 + kz]        = make_float2(rc - rs, is_ + ic);
            B2s[(64 - wp) * 9 + kz] = make_float2(rc + rs, ic - is_);
        } else if (j < 288) {
            const int kz = j - 279;                // w = 0: twiddle = 1
            float re = 0.f, im = 0.f;
            #pragma unroll
            for (int ky = 0; ky < 16; ky++) {
                float2 Yv = Yrow[ky * 9 + kz];
                re += Yv.x; im += Yv.y;
            }
            B2s[kz] = make_float2(re, im);
        } else {
            const int kz = j - 288;                // w = 32: twiddle = (-1)^ky
            float re = 0.f, im = 0.f;
            #pragma unroll
            for (int ky = 0; ky < 16; ky++) {
                float2 Yv = Yrow[ky * 9 + kz];
                float sg = (ky & 1) ? -1.0f : 1.0f;
                re = fmaf(Yv.x, sg, re); im = fmaf(Yv.y, sg, im);
            }
            B2s[32 * 9 + kz] = make_float2(re, im);
        }
    }
    __syncthreads();

    // Direct z-synthesis: thread (w0 = tid>>4, l = tid&15) computes d = l*4..l*4+3
    // for w = p*16 + w0, p = 0..3. Global I/O is float4 (512B/warp coalesced).
    const int l  = tid & 15;
    const int w0 = tid >> 4;
    const int d0 = l * 4;
    const size_t base = (size_t)plane * 4096;
    #pragma unroll
    for (int p = 0; p < 4; p++) {
        const int w = p * 16 + w0;
        const float2* Br = &B2s[w * 9];          // 2 addresses per warp: broadcast
        const float b0 = Br[0].x;
        float2 br[8];
        #pragma unroll
        for (int kz = 1; kz <= 8; kz++) br[kz - 1] = Br[kz];
        const float4 xv = *(const float4*)(x + base + w * 64 + d0);
        float s0 = 0.f, s1 = 0.f, s2 = 0.f, s3 = 0.f;
        #pragma unroll
        for (int kz = 0; kz < 8; kz++) {
            const float4 C = *(const float4*)&Csyn[kz * 64 + d0];
            const float4 S = *(const float4*)&Ssyn[kz * 64 + d0];
            const float2 b = br[kz];
            s0 = fmaf(b.x, C.x, s0); s0 = fmaf(-b.y, S.x, s0);
            s1 = fmaf(b.x, C.y, s1); s1 = fmaf(-b.y, S.y, s1);
            s2 = fmaf(b.x, C.z, s2); s2 = fmaf(-b.y, S.z, s2);
            s3 = fmaf(b.x, C.w, s3); s3 = fmaf(-b.y, S.w, s3);
        }
        float4 ov;
        ov.x = xv.x + fmaf(2.0f, s0, b0);
        ov.y = xv.y + fmaf(2.0f, s1, b0);
        ov.z = xv.z + fmaf(2.0f, s2, b0);
        ov.w = xv.w + fmaf(2.0f, s3, b0);
        *(float4*)(out + base + w * 64 + d0) = ov;
    }
}

// ---------------------------------------------------------------------------
extern "C" void kernel_launch(void* const* d_in, const int* in_sizes, int n_in,
                              void* d_out, int out_size) {
    const float* x  = (const float*)d_in[0];
    const float* w1 = (const float*)d_in[1];
    const float* b1 = (const float*)d_in[2];
    const float* w2 = (const float*)d_in[3];
    const float* b2 = (const float*)d_in[4];
    float* out = (float*)d_out;

    k_fwd<<<NPLANES, 256>>>(x);
    k_gates<<<1, 256>>>(w1, b1, w2, b2);
    k_xstage<<<1024, 256>>>();
    k_inv<<<NPLANES, 256>>>(x, out);
}

// round 15
// speedup vs baseline: 1.6320x; 1.0010x over previous
#include <cuda_runtime.h>
#include <math.h>

// x: [B=4, C=64, H=64, W=64, D=64] fp32
// out = x + irfftn(delta), delta = (gate-1)*rfftn(x) on corner [16,16,9]
#define NPLANES 16384   // B*C*H
#define GATE_DIM 2304   // 16*16*9
#define NCOL    144     // 16 ky * 9 kz

__device__ float2 g_Y[NPLANES * NCOL];     // 18.9 MB intermediate spectrum
__device__ float  g_planesum[NPLANES];
__device__ float  g_gate[4 * GATE_DIM];    // (sigmoid-1)/64^3

#define INV_N3 (1.0f / 262144.0f)

// Compile-time twiddles: TWC[t] = cos(2*pi*t/64); sin(t) = TWC[(t+48)&63]
__device__ constexpr float TWC[64] = {
     1.00000000f,  0.99518473f,  0.98078528f,  0.95694034f,
     0.92387953f,  0.88192126f,  0.83146961f,  0.77301045f,
     0.70710678f,  0.63439328f,  0.55557023f,  0.47139674f,
     0.38268343f,  0.29028468f,  0.19509032f,  0.09801714f,
     0.00000000f, -0.09801714f, -0.19509032f, -0.29028468f,
    -0.38268343f, -0.47139674f, -0.55557023f, -0.63439328f,
    -0.70710678f, -0.77301045f, -0.83146961f, -0.88192126f,
    -0.92387953f, -0.95694034f, -0.98078528f, -0.99518473f,
    -1.00000000f, -0.99518473f, -0.98078528f, -0.95694034f,
    -0.92387953f, -0.88192126f, -0.83146961f, -0.77301045f,
    -0.70710678f, -0.63439328f, -0.55557023f, -0.47139674f,
    -0.38268343f, -0.29028468f, -0.19509032f, -0.09801714f,
     0.00000000f,  0.09801714f,  0.19509032f,  0.29028468f,
     0.38268343f,  0.47139674f,  0.55557023f,  0.63439328f,
     0.70710678f,  0.77301045f,  0.83146961f,  0.88192126f,
     0.92387953f,  0.95694034f,  0.98078528f,  0.99518473f
};
__device__ __forceinline__ constexpr float twc(int t) { return TWC[t & 63]; }
__device__ __forceinline__ constexpr float tws(int t) { return TWC[(t + 48) & 63]; }

__device__ __forceinline__ void fill_tw(float2* tw, int tid) {
    if (tid < 64) {
        float s, c;
        sincospif((float)tid * (1.0f / 32.0f), &s, &c);
        tw[tid] = make_float2(c, s);
    }
}

// Advance complex rotation (tc, ts) by step (sx, sy): t *= s
#define ROT_ADV(tc, ts, sx, sy) do {                 \
    float _p = (ts) * (sy);                          \
    float _n = fmaf((tc), (sx), -_p);                \
    (ts) = fmaf((tc), (sy), (ts) * (sx));            \
    (tc) = _n;                                       \
} while (0)

// Folded z-DFT chunk: dp in [DP0, DP0+NDP), all 9 kz, compile-time twiddles.
template<int DP0, int NDP>
__device__ __forceinline__ void zchunk(const float* __restrict__ row,
                                       float* re, float* im) {
    #pragma unroll
    for (int i = 0; i < NDP; i++) {
        const int dp = DP0 + i;
        const float a = row[dp], b = row[64 - dp];
        const float e = a + b, o = a - b;
        re[0] += e;
        #pragma unroll
        for (int kz = 1; kz < 9; kz++) {
            re[kz] = fmaf(e, twc(kz * dp), re[kz]);
            im[kz] = fmaf(o, -tws(kz * dp), im[kz]);
        }
    }
}

// ---------------------------------------------------------------------------
// Kernel 1: per-plane: plane sum, z-DFT (immediate twiddles), y-DFT with
// twiddle recurrence.
// ---------------------------------------------------------------------------
__global__ void __launch_bounds__(256) k_fwd(const float* __restrict__ x) {
    __shared__ __align__(16) float xs[64 * 65];   // [w][d] stride 65; reused as Zs
    __shared__ float2 Zpart[4 * 64 * 9];          // [q][w][kz]
    __shared__ float2 tw[64];
    __shared__ float  red[8];
    float2* Zs = (float2*)xs;

    const int plane = blockIdx.x;
    const int tid   = threadIdx.x;
    fill_tw(tw, tid);

    const float4* xp4 = (const float4*)(x + (size_t)plane * 4096);
    float psum = 0.0f;
    #pragma unroll
    for (int k = 0; k < 4; k++) {
        const int i4 = k * 256 + tid;
        float4 v = xp4[i4];
        const int base = i4 * 4;
        float* dst = &xs[(base >> 6) * 65 + (base & 63)];
        dst[0] = v.x; dst[1] = v.y; dst[2] = v.z; dst[3] = v.w;
        psum += (v.x + v.y) + (v.z + v.w);
    }
    #pragma unroll
    for (int o = 16; o > 0; o >>= 1) psum += __shfl_down_sync(0xffffffffu, psum, o);
    if ((tid & 31) == 0) red[tid >> 5] = psum;
    __syncthreads();
    if (tid == 0) {
        float s = 0.0f;
        #pragma unroll
        for (int i = 0; i < 8; i++) s += red[i];
        g_planesum[plane] = s;
    }

    {
        const int w = tid & 63;
        const int q = tid >> 6;
        float re[9], im[9];
        #pragma unroll
        for (int kz = 0; kz < 9; kz++) { re[kz] = 0.f; im[kz] = 0.f; }
        const float* row = &xs[w * 65];
        if (q == 0)      zchunk<1, 8>(row, re, im);
        else if (q == 1) zchunk<9, 8>(row, re, im);
        else if (q == 2) zchunk<17, 8>(row, re, im);
        else {
            zchunk<25, 7>(row, re, im);
            const float x0 = row[0], x32 = row[32];
            #pragma unroll
            for (int kz = 0; kz < 9; kz++)
                re[kz] += x0 + ((kz & 1) ? -x32 : x32);
        }
        float2* zp = &Zpart[(q * 64 + w) * 9];
        #pragma unroll
        for (int kz = 0; kz < 9; kz++) zp[kz] = make_float2(re[kz], im[kz]);
    }
    __syncthreads();

    for (int j = tid; j < 576; j += 256) {
        const int ww = j / 9, kz = j - ww * 9;
        float2 a = Zpart[ww * 9 + kz];
        float2 b = Zpart[(64 + ww) * 9 + kz];
        float2 c = Zpart[(128 + ww) * 9 + kz];
        float2 d = Zpart[(192 + ww) * 9 + kz];
        Zs[ww * 9 + kz] = make_float2((a.x + b.x) + (c.x + d.x),
                                      (a.y + b.y) + (c.y + d.y));
    }
    __syncthreads();

    if (tid < NCOL) {
        const int ky = tid / 9;
        const int kz = tid % 9;
        const float sg = (ky & 1) ? -1.0f : 1.0f;
        float2 z0 = Zs[kz], z32 = Zs[32 * 9 + kz];
        float re = fmaf(sg, z32.x, z0.x);
        float im = fmaf(sg, z32.y, z0.y);
        const float2 st = tw[ky];        // step: angle ky per wp
        float tc = st.x, ts = st.y;      // twiddle for wp = 1
        #pragma unroll 31
        for (int wp = 1; wp <= 31; wp++) {
            float2 za = Zs[wp * 9 + kz];
            float2 zb = Zs[(64 - wp) * 9 + kz];
            float sx = za.x + zb.x, dxx = za.x - zb.x;
            float sy = za.y + zb.y, dy  = za.y - zb.y;
            re = fmaf(sx, tc, re); re = fmaf(dy, ts, re);
            im = fmaf(sy, tc, im); im = fmaf(-dxx, ts, im);
            ROT_ADV(tc, ts, st.x, st.y);
        }
        g_Y[(size_t)plane * NCOL + tid] = make_float2(re, im);
    }
}

// ---------------------------------------------------------------------------
// Kernel 2: gate MLP (single block)
// ---------------------------------------------------------------------------
__global__ void __launch_bounds__(256) k_gates(const float* __restrict__ w1,
                                               const float* __restrict__ b1,
                                               const float* __restrict__ w2,
                                               const float* __restrict__ b2) {
    __shared__ float pooled_s[256];
    __shared__ float hid_s[64];
    const int tid = threadIdx.x;
    {
        float s = 0.0f;
        const float* ps = &g_planesum[tid * 64];
        #pragma unroll 8
        for (int h = 0; h < 64; h++) s += ps[h];
        pooled_s[tid] = s * INV_N3;
    }
    __syncthreads();
    if (tid < 64) {
        const int b = tid >> 4, j = tid & 15;
        float acc = b1[j];
        #pragma unroll 8
        for (int c = 0; c < 64; c++) acc = fmaf(pooled_s[b * 64 + c], w1[c * 16 + j], acc);
        hid_s[tid] = fmaxf(acc, 0.0f);
    }
    __syncthreads();
    for (int j2 = tid; j2 < 4 * GATE_DIM; j2 += 256) {
        const int b = j2 / GATE_DIM, m = j2 % GATE_DIM;
        float acc = b2[m];
        #pragma unroll
        for (int j = 0; j < 16; j++) acc = fmaf(hid_s[b * 16 + j], w2[j * GATE_DIM + m], acc);
        float sig = 1.0f / (1.0f + expf(-acc));
        g_gate[j2] = (sig - 1.0f) * INV_N3;
    }
}

// ---------------------------------------------------------------------------
// Kernel 3: per (bc, 36-mode chunk): folded x-DFT -> gate -> folded x-inverse
// with twiddle recurrences in both phases.
// ---------------------------------------------------------------------------
#define MCH 36
__global__ void __launch_bounds__(256) k_xstage() {
    __shared__ float2 Ys[64 * MCH];
    __shared__ float2 As[MCH * 17];
    __shared__ float2 tw[64];

    const int bx  = blockIdx.x;
    const int bc  = bx >> 2;
    const int b   = bc >> 6;
    const int m0  = (bx & 3) * MCH;
    const int tid = threadIdx.x;
    fill_tw(tw, tid);

    float2* Yg = &g_Y[(size_t)bc * 64 * NCOL];
    for (int j = tid; j < 64 * MCH; j += 256) {
        const int h = j / MCH, mL = j % MCH;
        Ys[j] = Yg[h * NCOL + m0 + mL];
    }
    __syncthreads();

    for (int j = tid; j < MCH * 16; j += 256) {
        const int kx = j / MCH;
        const int mL = j % MCH;
        const float sg = (kx & 1) ? -1.0f : 1.0f;
        float2 z0 = Ys[mL], z32 = Ys[32 * MCH + mL];
        float re = fmaf(sg, z32.x, z0.x);
        float im = fmaf(sg, z32.y, z0.y);
        const float2 st = tw[kx];       // step per hp
        float tc = st.x, ts = st.y;     // twiddle for hp = 1
        #pragma unroll 31
        for (int hp = 1; hp <= 31; hp++) {
            float2 za = Ys[hp * MCH + mL];
            float2 zb = Ys[(64 - hp) * MCH + mL];
            float sx = za.x + zb.x, dxx = za.x - zb.x;
            float sy = za.y + zb.y, dy  = za.y - zb.y;
            re = fmaf(sx, tc, re); re = fmaf(dy, ts, re);
            im = fmaf(sy, tc, im); im = fmaf(-dxx, ts, im);
            ROT_ADV(tc, ts, st.x, st.y);
        }
        float gate = g_gate[b * GATE_DIM + kx * NCOL + m0 + mL];
        As[mL * 17 + kx] = make_float2(re * gate, im * gate);
    }
    __syncthreads();

    for (int j = tid; j < 32 * MCH; j += 256) {
        const int hp = j / MCH;
        const int mL = j % MCH;
        float P = 0.f, Q = 0.f, R = 0.f, S = 0.f;
        const float2 st = tw[hp];       // step per kx
        float tc = 1.f, ts = 0.f;       // twiddle for kx = 0
        #pragma unroll
        for (int kx = 0; kx < 16; kx++) {
            float2 A = As[mL * 17 + kx];
            P = fmaf(A.x, tc, P); Q = fmaf(A.y, ts, Q);
            R = fmaf(A.y, tc, R); S = fmaf(A.x, ts, S);
            ROT_ADV(tc, ts, st.x, st.y);
        }
        if (hp == 0) {
            float P32 = 0.f, R32 = 0.f;
            #pragma unroll
            for (int kx = 0; kx < 16; kx++) {
                float2 A = As[mL * 17 + kx];
                float sg = (kx & 1) ? -1.0f : 1.0f;
                P32 = fmaf(A.x, sg, P32); R32 = fmaf(A.y, sg, R32);
            }
            Yg[m0 + mL]             = make_float2(P, R);
            Yg[32 * NCOL + m0 + mL] = make_float2(P32, R32);
        } else {
            Yg[hp * NCOL + m0 + mL]        = make_float2(P - Q, S + R);
            Yg[(64 - hp) * NCOL + m0 + mL] = make_float2(P + Q, R - S);
        }
    }
}

// ---------------------------------------------------------------------------
// Kernel 4: per-plane: y-inverse (twiddle recurrence) -> B2s[w][kz] ->
// z-synthesis restructured kz-outer: C/S tables loaded ONCE per kz and
// reused across all 4 w-rows (16 accumulators). float4 global I/O epilogue.
// ---------------------------------------------------------------------------
__global__ void __launch_bounds__(256) k_inv(const float* __restrict__ x,
                                             float* __restrict__ out) {
    __shared__ float2 Yrow[NCOL];                 // [ky*9+kz]
    __shared__ float2 B2s[64 * 9];                // [w][kz], stride 9
    __shared__ float2 tw[64];
    __shared__ __align__(16) float Csyn[8 * 64];  // [kz-1][d]
    __shared__ __align__(16) float Ssyn[8 * 64];

    const int plane = blockIdx.x;
    const int tid   = threadIdx.x;
    fill_tw(tw, tid);

    // Build synthesis tables: Csyn[kz-1][d] = cos(2pi kz d/64), Ssyn = sin
    for (int e = tid; e < 512; e += 256) {
        const int kz = (e >> 6) + 1;
        const int d  = e & 63;
        float s, c;
        sincospif((float)((kz * d) & 63) * (1.0f / 32.0f), &s, &c);
        Csyn[e] = c; Ssyn[e] = s;
    }
    if (tid < NCOL) Yrow[tid] = g_Y[(size_t)plane * NCOL + tid];
    __syncthreads();

    // Folded y-inverse: tasks 0..278 generic pairs, 279..287 w=0, 288..296 w=32
    for (int j = tid; j < 297; j += 256) {
        if (j < 279) {
            const int wp = j / 9 + 1;
            const int kz = j - (wp - 1) * 9;
            const float2 st = tw[wp];       // step per ky
            float2 Y0 = Yrow[kz];
            float rc = Y0.x, rs = 0.f, ic = Y0.y, is_ = 0.f;
            float tc = st.x, ts = st.y;     // twiddle for ky = 1
            #pragma unroll 15
            for (int ky = 1; ky < 16; ky++) {
                float2 Yv = Yrow[ky * 9 + kz];
                rc = fmaf(Yv.x, tc, rc); rs  = fmaf(Yv.y, ts, rs);
                ic = fmaf(Yv.y, tc, ic); is_ = fmaf(Yv.x, ts, is_);
                ROT_ADV(tc, ts, st.x, st.y);
            }
            B2s[wp * 9 + kz]        = make_float2(rc - rs, is_ + ic);
            B2s[(64 - wp) * 9 + kz] = make_float2(rc + rs, ic - is_);
        } else if (j < 288) {
            const int kz = j - 279;                // w = 0: twiddle = 1
            float re = 0.f, im = 0.f;
            #pragma unroll
            for (int ky = 0; ky < 16; ky++) {
                float2 Yv = Yrow[ky * 9 + kz];
                re += Yv.x; im += Yv.y;
            }
            B2s[kz] = make_float2(re, im);
        } else {
            const int kz = j - 288;                // w = 32: twiddle = (-1)^ky
            float re = 0.f, im = 0.f;
            #pragma unroll
            for (int ky = 0; ky < 16; ky++) {
                float2 Yv = Yrow[ky * 9 + kz];
                float sg = (ky & 1) ? -1.0f : 1.0f;
                re = fmaf(Yv.x, sg, re); im = fmaf(Yv.y, sg, im);
            }
            B2s[32 * 9 + kz] = make_float2(re, im);
        }
    }
    __syncthreads();

    // z-synthesis, kz-outer: thread (w0 = tid>>4, l = tid&15), d = l*4..l*4+3,
    // w = p*16 + w0 for p = 0..3. Tables loaded once per kz (2 LDS.128),
    // shared by all 4 w-rows. 16 accumulators.
    const int l  = tid & 15;
    const int w0 = tid >> 4;
    const int d0 = l * 4;
    float acc[4][4];
    #pragma unroll
    for (int p = 0; p < 4; p++) {
        acc[p][0] = 0.f; acc[p][1] = 0.f; acc[p][2] = 0.f; acc[p][3] = 0.f;
    }
    #pragma unroll
    for (int kz = 0; kz < 8; kz++) {
        const float4 C = *(const float4*)&Csyn[kz * 64 + d0];
        const float4 S = *(const float4*)&Ssyn[kz * 64 + d0];
        #pragma unroll
        for (int p = 0; p < 4; p++) {
            const float2 b = B2s[(p * 16 + w0) * 9 + kz + 1];  // broadcast
            acc[p][0] = fmaf(b.x, C.x, acc[p][0]); acc[p][0] = fmaf(-b.y, S.x, acc[p][0]);
            acc[p][1] = fmaf(b.x, C.y, acc[p][1]); acc[p][1] = fmaf(-b.y, S.y, acc[p][1]);
            acc[p][2] = fmaf(b.x, C.z, acc[p][2]); acc[p][2] = fmaf(-b.y, S.z, acc[p][2]);
            acc[p][3] = fmaf(b.x, C.w, acc[p][3]); acc[p][3] = fmaf(-b.y, S.w, acc[p][3]);
        }
    }
    const size_t base = (size_t)plane * 4096;
    #pragma unroll
    for (int p = 0; p < 4; p++) {
        const int w = p * 16 + w0;
        const float b0 = B2s[w * 9].x;             // broadcast
        const float4 xv = *(const float4*)(x + base + w * 64 + d0);
        float4 ov;
        ov.x = xv.x + fmaf(2.0f, acc[p][0], b0);
        ov.y = xv.y + fmaf(2.0f, acc[p][1], b0);
        ov.z = xv.z + fmaf(2.0f, acc[p][2], b0);
        ov.w = xv.w + fmaf(2.0f, acc[p][3], b0);
        *(float4*)(out + base + w * 64 + d0) = ov;
    }
}

// ---------------------------------------------------------------------------
extern "C" void kernel_launch(void* const* d_in, const int* in_sizes, int n_in,
                              void* d_out, int out_size) {
    const float* x  = (const float*)d_in[0];
    const float* w1 = (const float*)d_in[1];
    const float* b1 = (const float*)d_in[2];
    const float* w2 = (const float*)d_in[3];
    const float* b2 = (const float*)d_in[4];
    float* out = (float*)d_out;

    k_fwd<<<NPLANES, 256>>>(x);
    k_gates<<<1, 256>>>(w1, b1, w2, b2);
    k_xstage<<<1024, 256>>>();
    k_inv<<<NPLANES, 256>>>(x, out);
}